// round 1
// baseline (speedup 1.0000x reference)
#include <cuda_runtime.h>
#include <math.h>

#define NB   2
#define NH   16
#define SEQ  2048
#define HD   64
#define DM   1024
#define SCALE 0.125f   // 64^-0.5

// ---- scratch (device globals; no allocation APIs allowed) ----
__device__ float g_qr[NB*NH*SEQ*HD];   // 16 MB
__device__ float g_kr[NB*NH*SEQ*HD];   // 16 MB
__device__ float g_qt[NB*NH*SEQ*HD];   // 16 MB
__device__ float g_ctx[NB*SEQ*DM];     // 16 MB  (b, s, h*d) layout for the final GEMM

// ============================================================
// 1) RoPE: one warp per (b,h,s) row; lane l handles dims l and l+32
// ============================================================
__global__ __launch_bounds__(256) void rope_kernel(const float* __restrict__ q,
                                                   const float* __restrict__ k) {
    int warp = threadIdx.x >> 5;
    int lane = threadIdx.x & 31;
    int row  = blockIdx.x * 8 + warp;          // < NB*NH*SEQ
    int pos  = row & (SEQ - 1);
    float inv_freq = 1.0f / powf(10000.0f, (float)(2 * lane) * (1.0f / 64.0f));
    float sn, cs;
    sincosf((float)pos * inv_freq, &sn, &cs);
    size_t base = (size_t)row * HD;
    float a1 = q[base + lane], a2 = q[base + lane + 32];
    g_qr[base + lane]      = a1 * cs - a2 * sn;
    g_qr[base + lane + 32] = a2 * cs + a1 * sn;
    float b1 = k[base + lane], b2 = k[base + lane + 32];
    g_kr[base + lane]      = b1 * cs - b2 * sn;
    g_kr[base + lane + 32] = b2 * cs + b1 * sn;
}

// ============================================================
// 2) qt[b,h] = W[h] (2048x2048, K-major) @ qr[b,h] (2048x64)
//    128x64 C-tile per block, 128 threads, 8x8 micro-tile, Kc=32
// ============================================================
__global__ __launch_bounds__(128) void qt_gemm_kernel(const float* __restrict__ mask) {
    __shared__ float aT[32][132];   // W chunk, transposed [kk][row]
    __shared__ float bS[32][64];    // qr chunk, natural  [kk][d]
    int t  = threadIdx.x;
    int ty = t >> 3;                // rows ty*8
    int tx = t & 7;                 // cols tx*8
    int bh = blockIdx.y;            // b*NH + h
    int h  = bh & (NH - 1);
    int row0 = blockIdx.x * 128;
    const float* Wp = mask + (size_t)h * SEQ * SEQ + (size_t)row0 * SEQ;
    const float* Bp = g_qr + (size_t)bh * SEQ * HD;

    float acc[8][8];
#pragma unroll
    for (int r = 0; r < 8; r++)
#pragma unroll
        for (int c = 0; c < 8; c++) acc[r][c] = 0.f;

    for (int k0 = 0; k0 < SEQ; k0 += 32) {
#pragma unroll
        for (int j = 0; j < 8; j++) {
            int f = j * 128 + t;
            int row = f >> 3, kg = f & 7;
            float4 w4 = *(const float4*)(Wp + (size_t)row * SEQ + k0 + kg * 4);
            aT[kg*4+0][row] = w4.x; aT[kg*4+1][row] = w4.y;
            aT[kg*4+2][row] = w4.z; aT[kg*4+3][row] = w4.w;
        }
#pragma unroll
        for (int j = 0; j < 4; j++) {
            int f = j * 128 + t;
            int kk = f >> 4, dg = f & 15;
            *(float4*)&bS[kk][dg*4] = *(const float4*)(Bp + (size_t)(k0 + kk) * HD + dg * 4);
        }
        __syncthreads();
#pragma unroll 8
        for (int kk = 0; kk < 32; kk++) {
            float4 a0 = *(const float4*)&aT[kk][ty*8];
            float4 a1 = *(const float4*)&aT[kk][ty*8+4];
            float4 b0 = *(const float4*)&bS[kk][tx*8];
            float4 b1 = *(const float4*)&bS[kk][tx*8+4];
            float av[8] = {a0.x,a0.y,a0.z,a0.w,a1.x,a1.y,a1.z,a1.w};
            float bv[8] = {b0.x,b0.y,b0.z,b0.w,b1.x,b1.y,b1.z,b1.w};
#pragma unroll
            for (int r = 0; r < 8; r++)
#pragma unroll
                for (int c = 0; c < 8; c++) acc[r][c] += av[r] * bv[c];
        }
        __syncthreads();
    }
    float* outp = g_qt + (size_t)bh * SEQ * HD + (size_t)row0 * HD;
#pragma unroll
    for (int r = 0; r < 8; r++) {
        int row = ty * 8 + r;
        *(float4*)(outp + (size_t)row * HD + tx*8)     = make_float4(acc[r][0],acc[r][1],acc[r][2],acc[r][3]);
        *(float4*)(outp + (size_t)row * HD + tx*8 + 4) = make_float4(acc[r][4],acc[r][5],acc[r][6],acc[r][7]);
    }
}

// ============================================================
// 3) Flash attention: per (b,h, 64-row q tile); BK=64, d=64.
//    256 threads (16x16), 4x4 micro-tiles for S and O.
//    kS uses XOR swizzle to make both the transposed-ish reads and
//    writes bank-clean. Dynamic smem: 4 * 64*64 floats = 64 KB.
// ============================================================
__global__ __launch_bounds__(256) void flash_kernel(const float* __restrict__ v) {
    extern __shared__ float sm[];
    float* qS = sm;                 // [row][d]  natural, pre-scaled
    float* kS = sm + 64*64;         // [col][d]  d XOR-swizzled by col
    float* vS = sm + 2*64*64;       // [k][d]    natural
    float* pS = sm + 3*64*64;       // [row][k]  natural

    int t  = threadIdx.x;
    int ty = t >> 4;                // rows ty*4
    int tx = t & 15;                // cols tx*4
    int bh = blockIdx.y;
    int b  = bh >> 4, h = bh & 15;
    int q0 = blockIdx.x * 64;

    const float* qtp = g_qt + ((size_t)bh * SEQ + q0) * HD;
    const float* kp  = g_kr + (size_t)bh * SEQ * HD;
    const float* vp  = v    + (size_t)bh * SEQ * HD;

#pragma unroll
    for (int j = 0; j < 4; j++) {
        int f = j * 256 + t;
        int row = f >> 4, dg = f & 15;
        float4 qv = *(const float4*)(qtp + (size_t)row * HD + dg * 4);
        qv.x *= SCALE; qv.y *= SCALE; qv.z *= SCALE; qv.w *= SCALE;
        *(float4*)&qS[row*64 + dg*4] = qv;
    }

    float m[4], l[4], acc[4][4];
#pragma unroll
    for (int r = 0; r < 4; r++) {
        m[r] = -1e30f; l[r] = 0.f;
#pragma unroll
        for (int c = 0; c < 4; c++) acc[r][c] = 0.f;
    }

    int swz = 4 * (tx & 7);   // this thread's 4 k-columns share one swizzle
    for (int kt = 0; kt < SEQ / 64; kt++) {
        int k0 = kt * 64;
#pragma unroll
        for (int j = 0; j < 4; j++) {
            int f = j * 256 + t;
            int row = f >> 4, dg = f & 15;
            float4 kv = *(const float4*)(kp + (size_t)(k0 + row) * HD + dg * 4);
            int dsw = (dg * 4) ^ (4 * ((row >> 2) & 7));
            *(float4*)&kS[row*64 + dsw]  = kv;
            *(float4*)&vS[row*64 + dg*4] = *(const float4*)(vp + (size_t)(k0 + row) * HD + dg * 4);
        }
        __syncthreads();

        // S = (qt*scale) @ k^T  (64x64x64)
        float s[4][4];
#pragma unroll
        for (int r = 0; r < 4; r++)
#pragma unroll
            for (int c = 0; c < 4; c++) s[r][c] = 0.f;
#pragma unroll 4
        for (int dd = 0; dd < 64; dd += 4) {
            float4 qv[4], kv[4];
#pragma unroll
            for (int r = 0; r < 4; r++) qv[r] = *(const float4*)&qS[(ty*4+r)*64 + dd];
#pragma unroll
            for (int c = 0; c < 4; c++) kv[c] = *(const float4*)&kS[(tx*4+c)*64 + (dd ^ swz)];
#pragma unroll
            for (int r = 0; r < 4; r++)
#pragma unroll
                for (int c = 0; c < 4; c++)
                    s[r][c] += qv[r].x*kv[c].x + qv[r].y*kv[c].y
                             + qv[r].z*kv[c].z + qv[r].w*kv[c].w;
        }

        // online softmax (row groups = 16 lanes sharing ty)
#pragma unroll
        for (int r = 0; r < 4; r++) {
            float rm = fmaxf(fmaxf(s[r][0], s[r][1]), fmaxf(s[r][2], s[r][3]));
#pragma unroll
            for (int o = 1; o < 16; o <<= 1)
                rm = fmaxf(rm, __shfl_xor_sync(0xffffffffu, rm, o));
            float mn   = fmaxf(m[r], rm);
            float corr = __expf(m[r] - mn);
            float rs = 0.f;
#pragma unroll
            for (int c = 0; c < 4; c++) {
                float p = __expf(s[r][c] - mn);
                s[r][c] = p; rs += p;
            }
#pragma unroll
            for (int o = 1; o < 16; o <<= 1)
                rs += __shfl_xor_sync(0xffffffffu, rs, o);
            l[r] = l[r] * corr + rs;
            m[r] = mn;
#pragma unroll
            for (int c = 0; c < 4; c++) acc[r][c] *= corr;
        }
#pragma unroll
        for (int r = 0; r < 4; r++)
            *(float4*)&pS[(ty*4+r)*64 + tx*4] = make_float4(s[r][0], s[r][1], s[r][2], s[r][3]);
        __syncthreads();

        // O += P @ V  (64x64x64)
#pragma unroll 8
        for (int kk = 0; kk < 64; kk++) {
            float4 vv = *(const float4*)&vS[kk*64 + tx*4];
            float p0 = pS[(ty*4+0)*64 + kk];
            float p1 = pS[(ty*4+1)*64 + kk];
            float p2 = pS[(ty*4+2)*64 + kk];
            float p3 = pS[(ty*4+3)*64 + kk];
            acc[0][0] += p0*vv.x; acc[0][1] += p0*vv.y; acc[0][2] += p0*vv.z; acc[0][3] += p0*vv.w;
            acc[1][0] += p1*vv.x; acc[1][1] += p1*vv.y; acc[1][2] += p1*vv.z; acc[1][3] += p1*vv.w;
            acc[2][0] += p2*vv.x; acc[2][1] += p2*vv.y; acc[2][2] += p2*vv.z; acc[2][3] += p2*vv.w;
            acc[3][0] += p3*vv.x; acc[3][1] += p3*vv.y; acc[3][2] += p3*vv.z; acc[3][3] += p3*vv.w;
        }
        __syncthreads();
    }

    // write ctx in (b, s, h*d) layout
    float* cp = g_ctx + ((size_t)b * SEQ + q0) * DM + h * HD;
#pragma unroll
    for (int r = 0; r < 4; r++) {
        float invl = 1.0f / l[r];
        *(float4*)(cp + (size_t)(ty*4 + r) * DM + tx*4) =
            make_float4(acc[r][0]*invl, acc[r][1]*invl, acc[r][2]*invl, acc[r][3]*invl);
    }
}

// ============================================================
// 4) out = ctx (4096x1024) @ out_w^T (1024x1024, K-major) + out_b
//    128x64 tile, 128 threads, 8x8 micro, Kc=32; both operands K-major
// ============================================================
__global__ __launch_bounds__(128) void out_gemm_kernel(const float* __restrict__ w,
                                                       const float* __restrict__ bias,
                                                       float* __restrict__ out) {
    __shared__ float aT[32][132];
    __shared__ float bT[32][68];
    int t  = threadIdx.x;
    int ty = t >> 3, tx = t & 7;
    int row0 = blockIdx.x * 128;
    int col0 = blockIdx.y * 64;
    const float* Ap = g_ctx + (size_t)row0 * DM;
    const float* Bp = w     + (size_t)col0 * DM;

    float acc[8][8];
#pragma unroll
    for (int r = 0; r < 8; r++)
#pragma unroll
        for (int c = 0; c < 8; c++) acc[r][c] = 0.f;

    for (int k0 = 0; k0 < DM; k0 += 32) {
#pragma unroll
        for (int j = 0; j < 8; j++) {
            int f = j * 128 + t;
            int row = f >> 3, kg = f & 7;
            float4 a4 = *(const float4*)(Ap + (size_t)row * DM + k0 + kg * 4);
            aT[kg*4+0][row] = a4.x; aT[kg*4+1][row] = a4.y;
            aT[kg*4+2][row] = a4.z; aT[kg*4+3][row] = a4.w;
        }
#pragma unroll
        for (int j = 0; j < 4; j++) {
            int f = j * 128 + t;
            int col = f >> 3, kg = f & 7;
            float4 b4 = *(const float4*)(Bp + (size_t)col * DM + k0 + kg * 4);
            bT[kg*4+0][col] = b4.x; bT[kg*4+1][col] = b4.y;
            bT[kg*4+2][col] = b4.z; bT[kg*4+3][col] = b4.w;
        }
        __syncthreads();
#pragma unroll 8
        for (int kk = 0; kk < 32; kk++) {
            float4 a0 = *(const float4*)&aT[kk][ty*8];
            float4 a1 = *(const float4*)&aT[kk][ty*8+4];
            float4 b0 = *(const float4*)&bT[kk][tx*8];
            float4 b1 = *(const float4*)&bT[kk][tx*8+4];
            float av[8] = {a0.x,a0.y,a0.z,a0.w,a1.x,a1.y,a1.z,a1.w};
            float bv[8] = {b0.x,b0.y,b0.z,b0.w,b1.x,b1.y,b1.z,b1.w};
#pragma unroll
            for (int r = 0; r < 8; r++)
#pragma unroll
                for (int c = 0; c < 8; c++) acc[r][c] += av[r] * bv[c];
        }
        __syncthreads();
    }
    float4 bi0 = *(const float4*)(bias + col0 + tx*8);
    float4 bi1 = *(const float4*)(bias + col0 + tx*8 + 4);
#pragma unroll
    for (int r = 0; r < 8; r++) {
        size_t row = row0 + ty*8 + r;
        *(float4*)(out + row * DM + col0 + tx*8) =
            make_float4(acc[r][0]+bi0.x, acc[r][1]+bi0.y, acc[r][2]+bi0.z, acc[r][3]+bi0.w);
        *(float4*)(out + row * DM + col0 + tx*8 + 4) =
            make_float4(acc[r][4]+bi1.x, acc[r][5]+bi1.y, acc[r][6]+bi1.z, acc[r][7]+bi1.w);
    }
}

// ============================================================
extern "C" void kernel_launch(void* const* d_in, const int* in_sizes, int n_in,
                              void* d_out, int out_size) {
    (void)in_sizes; (void)n_in; (void)out_size;
    const float* q    = (const float*)d_in[0];
    const float* k    = (const float*)d_in[1];
    const float* v    = (const float*)d_in[2];
    const float* mask = (const float*)d_in[3];
    const float* ow   = (const float*)d_in[4];
    const float* ob   = (const float*)d_in[5];
    float* out = (float*)d_out;

    cudaFuncSetAttribute(flash_kernel, cudaFuncAttributeMaxDynamicSharedMemorySize,
                         4 * 64 * 64 * (int)sizeof(float));

    rope_kernel<<<NB * NH * SEQ / 8, 256>>>(q, k);
    qt_gemm_kernel<<<dim3(SEQ / 128, NB * NH), 128>>>(mask);
    flash_kernel<<<dim3(SEQ / 64, NB * NH), 256, 4 * 64 * 64 * sizeof(float)>>>(v);
    out_gemm_kernel<<<dim3(NB * SEQ / 128, DM / 64), 128>>>(ow, ob, out);
}

// round 2
// speedup vs baseline: 1.0194x; 1.0194x over previous
#include <cuda_runtime.h>
#include <math.h>

#define NB   2
#define NH   16
#define SEQ  2048
#define HD   64
#define DM   1024
#define SCALE 0.125f   // 64^-0.5

typedef unsigned long long u64;

// ---- packed f32x2 helpers (Blackwell-only PTX; ptxas never auto-fuses) ----
__device__ __forceinline__ u64 bcast2(float x) {
    u64 r; asm("mov.b64 %0, {%1, %1};" : "=l"(r) : "f"(x)); return r;
}
__device__ __forceinline__ u64 ffma2(u64 c, u64 a, u64 b) {
    u64 d; asm("fma.rn.f32x2 %0, %1, %2, %3;" : "=l"(d) : "l"(a), "l"(b), "l"(c)); return d;
}
__device__ __forceinline__ u64 fmul2(u64 a, u64 b) {
    u64 d; asm("mul.rn.f32x2 %0, %1, %2;" : "=l"(d) : "l"(a), "l"(b)); return d;
}
__device__ __forceinline__ float2 unpack2(u64 a) {
    float lo, hi; asm("mov.b64 {%0, %1}, %2;" : "=f"(lo), "=f"(hi) : "l"(a));
    return make_float2(lo, hi);
}

// ---- scratch (device globals; no allocation APIs allowed) ----
__device__ float g_qr[NB*NH*SEQ*HD];   // 16 MB
__device__ float g_kr[NB*NH*SEQ*HD];   // 16 MB
__device__ float g_qt[NB*NH*SEQ*HD];   // 16 MB
__device__ float g_ctx[NB*SEQ*DM];     // 16 MB  (b, s, h*d) layout for the final GEMM

// ============================================================
// 1) RoPE: one warp per (b,h,s) row; lane l handles dims l and l+32
// ============================================================
__global__ __launch_bounds__(256) void rope_kernel(const float* __restrict__ q,
                                                   const float* __restrict__ k) {
    int warp = threadIdx.x >> 5;
    int lane = threadIdx.x & 31;
    int row  = blockIdx.x * 8 + warp;          // < NB*NH*SEQ
    int pos  = row & (SEQ - 1);
    float inv_freq = 1.0f / powf(10000.0f, (float)(2 * lane) * (1.0f / 64.0f));
    float sn, cs;
    sincosf((float)pos * inv_freq, &sn, &cs);
    size_t base = (size_t)row * HD;
    float a1 = q[base + lane], a2 = q[base + lane + 32];
    g_qr[base + lane]      = a1 * cs - a2 * sn;
    g_qr[base + lane + 32] = a2 * cs + a1 * sn;
    float b1 = k[base + lane], b2 = k[base + lane + 32];
    g_kr[base + lane]      = b1 * cs - b2 * sn;
    g_kr[base + lane + 32] = b2 * cs + b1 * sn;
}

// ============================================================
// 2) qt[b,h] = W[h] (2048x2048, K-major) @ qr[b,h] (2048x64)
//    128x64 C-tile per block, 128 threads, 8x8 micro, packed f32x2
// ============================================================
__global__ __launch_bounds__(128) void qt_gemm_kernel(const float* __restrict__ mask) {
    __shared__ float aT[32][132];   // W chunk, transposed [kk][row]
    __shared__ float bS[32][64];    // qr chunk, natural  [kk][d]
    int t  = threadIdx.x;
    int ty = t >> 3;                // rows ty*8
    int tx = t & 7;                 // cols tx*8
    int bh = blockIdx.y;            // b*NH + h
    int h  = bh & (NH - 1);
    int row0 = blockIdx.x * 128;
    const float* Wp = mask + (size_t)h * SEQ * SEQ + (size_t)row0 * SEQ;
    const float* Bp = g_qr + (size_t)bh * SEQ * HD;

    u64 acc2[8][4];
#pragma unroll
    for (int r = 0; r < 8; r++)
#pragma unroll
        for (int c = 0; c < 4; c++) acc2[r][c] = 0ull;

    for (int k0 = 0; k0 < SEQ; k0 += 32) {
#pragma unroll
        for (int j = 0; j < 8; j++) {
            int f = j * 128 + t;
            int row = f >> 3, kg = f & 7;
            float4 w4 = *(const float4*)(Wp + (size_t)row * SEQ + k0 + kg * 4);
            aT[kg*4+0][row] = w4.x; aT[kg*4+1][row] = w4.y;
            aT[kg*4+2][row] = w4.z; aT[kg*4+3][row] = w4.w;
        }
#pragma unroll
        for (int j = 0; j < 4; j++) {
            int f = j * 128 + t;
            int kk = f >> 4, dg = f & 15;
            *(float4*)&bS[kk][dg*4] = *(const float4*)(Bp + (size_t)(k0 + kk) * HD + dg * 4);
        }
        __syncthreads();
#pragma unroll 8
        for (int kk = 0; kk < 32; kk++) {
            float4 a0 = *(const float4*)&aT[kk][ty*8];
            float4 a1 = *(const float4*)&aT[kk][ty*8+4];
            ulonglong2 b01 = *(const ulonglong2*)&bS[kk][tx*8];
            ulonglong2 b23 = *(const ulonglong2*)&bS[kk][tx*8+4];
            float av[8] = {a0.x,a0.y,a0.z,a0.w,a1.x,a1.y,a1.z,a1.w};
#pragma unroll
            for (int r = 0; r < 8; r++) {
                u64 ap = bcast2(av[r]);
                acc2[r][0] = ffma2(acc2[r][0], ap, b01.x);
                acc2[r][1] = ffma2(acc2[r][1], ap, b01.y);
                acc2[r][2] = ffma2(acc2[r][2], ap, b23.x);
                acc2[r][3] = ffma2(acc2[r][3], ap, b23.y);
            }
        }
        __syncthreads();
    }
    float* outp = g_qt + (size_t)bh * SEQ * HD + (size_t)row0 * HD;
#pragma unroll
    for (int r = 0; r < 8; r++) {
        int row = ty * 8 + r;
        float2 c0 = unpack2(acc2[r][0]), c1 = unpack2(acc2[r][1]);
        float2 c2 = unpack2(acc2[r][2]), c3 = unpack2(acc2[r][3]);
        *(float4*)(outp + (size_t)row * HD + tx*8)     = make_float4(c0.x, c0.y, c1.x, c1.y);
        *(float4*)(outp + (size_t)row * HD + tx*8 + 4) = make_float4(c2.x, c2.y, c3.x, c3.y);
    }
}

// ============================================================
// 3) Flash attention: per (b,h, 64-row q tile); BK=64, d=64.
//    256 threads (16x16), 4x4 micro, packed f32x2 mainloops.
// ============================================================
__global__ __launch_bounds__(256) void flash_kernel(const float* __restrict__ v) {
    extern __shared__ float sm[];
    float* qS = sm;                 // [row][d]  natural, pre-scaled
    float* kS = sm + 64*64;         // [col][d]  d XOR-swizzled by col-group
    float* vS = sm + 2*64*64;       // [k][d]    natural
    float* pS = sm + 3*64*64;       // [row][k]  natural

    int t  = threadIdx.x;
    int ty = t >> 4;                // rows ty*4
    int tx = t & 15;                // cols tx*4
    int bh = blockIdx.y;
    int b  = bh >> 4, h = bh & 15;
    int q0 = blockIdx.x * 64;

    const float* qtp = g_qt + ((size_t)bh * SEQ + q0) * HD;
    const float* kp  = g_kr + (size_t)bh * SEQ * HD;
    const float* vp  = v    + (size_t)bh * SEQ * HD;

#pragma unroll
    for (int j = 0; j < 4; j++) {
        int f = j * 256 + t;
        int row = f >> 4, dg = f & 15;
        float4 qv = *(const float4*)(qtp + (size_t)row * HD + dg * 4);
        qv.x *= SCALE; qv.y *= SCALE; qv.z *= SCALE; qv.w *= SCALE;
        *(float4*)&qS[row*64 + dg*4] = qv;
    }

    float m[4], l[4];
    u64 o2[4][2];
#pragma unroll
    for (int r = 0; r < 4; r++) {
        m[r] = -1e30f; l[r] = 0.f;
        o2[r][0] = 0ull; o2[r][1] = 0ull;
    }

    int swz = 4 * (tx & 7);   // this thread's 4 k-columns share one swizzle
    for (int kt = 0; kt < SEQ / 64; kt++) {
        int k0 = kt * 64;
#pragma unroll
        for (int j = 0; j < 4; j++) {
            int f = j * 256 + t;
            int row = f >> 4, dg = f & 15;
            float4 kv = *(const float4*)(kp + (size_t)(k0 + row) * HD + dg * 4);
            int dsw = (dg * 4) ^ (4 * ((row >> 2) & 7));
            *(float4*)&kS[row*64 + dsw]  = kv;
            *(float4*)&vS[row*64 + dg*4] = *(const float4*)(vp + (size_t)(k0 + row) * HD + dg * 4);
        }
        __syncthreads();

        // S = (qt*scale) @ k^T  (64x64x64), packed along d
        u64 s2[4][4];
#pragma unroll
        for (int r = 0; r < 4; r++)
#pragma unroll
            for (int c = 0; c < 4; c++) s2[r][c] = 0ull;
#pragma unroll 4
        for (int dd = 0; dd < 64; dd += 4) {
            ulonglong2 qv[4], kv[4];
#pragma unroll
            for (int r = 0; r < 4; r++) qv[r] = *(const ulonglong2*)&qS[(ty*4+r)*64 + dd];
#pragma unroll
            for (int c = 0; c < 4; c++) kv[c] = *(const ulonglong2*)&kS[(tx*4+c)*64 + (dd ^ swz)];
#pragma unroll
            for (int r = 0; r < 4; r++)
#pragma unroll
                for (int c = 0; c < 4; c++) {
                    s2[r][c] = ffma2(s2[r][c], qv[r].x, kv[c].x);
                    s2[r][c] = ffma2(s2[r][c], qv[r].y, kv[c].y);
                }
        }
        float s[4][4];
#pragma unroll
        for (int r = 0; r < 4; r++)
#pragma unroll
            for (int c = 0; c < 4; c++) {
                float2 f2 = unpack2(s2[r][c]);
                s[r][c] = f2.x + f2.y;
            }

        // online softmax (row groups = 16 lanes sharing ty)
#pragma unroll
        for (int r = 0; r < 4; r++) {
            float rm = fmaxf(fmaxf(s[r][0], s[r][1]), fmaxf(s[r][2], s[r][3]));
#pragma unroll
            for (int o = 1; o < 16; o <<= 1)
                rm = fmaxf(rm, __shfl_xor_sync(0xffffffffu, rm, o));
            float mn   = fmaxf(m[r], rm);
            float corr = __expf(m[r] - mn);
            float rs = 0.f;
#pragma unroll
            for (int c = 0; c < 4; c++) {
                float p = __expf(s[r][c] - mn);
                s[r][c] = p; rs += p;
            }
#pragma unroll
            for (int o = 1; o < 16; o <<= 1)
                rs += __shfl_xor_sync(0xffffffffu, rs, o);
            l[r] = l[r] * corr + rs;
            m[r] = mn;
            u64 cp = bcast2(corr);
            o2[r][0] = fmul2(o2[r][0], cp);
            o2[r][1] = fmul2(o2[r][1], cp);
        }
#pragma unroll
        for (int r = 0; r < 4; r++)
            *(float4*)&pS[(ty*4+r)*64 + tx*4] = make_float4(s[r][0], s[r][1], s[r][2], s[r][3]);
        __syncthreads();

        // O += P @ V  (64x64x64), packed along d
#pragma unroll 8
        for (int kk = 0; kk < 64; kk++) {
            ulonglong2 vv = *(const ulonglong2*)&vS[kk*64 + tx*4];
            u64 p0 = bcast2(pS[(ty*4+0)*64 + kk]);
            u64 p1 = bcast2(pS[(ty*4+1)*64 + kk]);
            u64 p2 = bcast2(pS[(ty*4+2)*64 + kk]);
            u64 p3 = bcast2(pS[(ty*4+3)*64 + kk]);
            o2[0][0] = ffma2(o2[0][0], p0, vv.x); o2[0][1] = ffma2(o2[0][1], p0, vv.y);
            o2[1][0] = ffma2(o2[1][0], p1, vv.x); o2[1][1] = ffma2(o2[1][1], p1, vv.y);
            o2[2][0] = ffma2(o2[2][0], p2, vv.x); o2[2][1] = ffma2(o2[2][1], p2, vv.y);
            o2[3][0] = ffma2(o2[3][0], p3, vv.x); o2[3][1] = ffma2(o2[3][1], p3, vv.y);
        }
        __syncthreads();
    }

    // write ctx in (b, s, h*d) layout
    float* cp = g_ctx + ((size_t)b * SEQ + q0) * DM + h * HD;
#pragma unroll
    for (int r = 0; r < 4; r++) {
        float invl = 1.0f / l[r];
        float2 a0 = unpack2(o2[r][0]), a1 = unpack2(o2[r][1]);
        *(float4*)(cp + (size_t)(ty*4 + r) * DM + tx*4) =
            make_float4(a0.x*invl, a0.y*invl, a1.x*invl, a1.y*invl);
    }
}

// ============================================================
// 4) out = ctx (4096x1024) @ out_w^T (1024x1024, K-major) + out_b
//    128x64 tile, 128 threads, 8x8 micro, packed f32x2
// ============================================================
__global__ __launch_bounds__(128) void out_gemm_kernel(const float* __restrict__ w,
                                                       const float* __restrict__ bias,
                                                       float* __restrict__ out) {
    __shared__ float aT[32][132];
    __shared__ float bT[32][68];
    int t  = threadIdx.x;
    int ty = t >> 3, tx = t & 7;
    int row0 = blockIdx.x * 128;
    int col0 = blockIdx.y * 64;
    const float* Ap = g_ctx + (size_t)row0 * DM;
    const float* Bp = w     + (size_t)col0 * DM;

    u64 acc2[8][4];
#pragma unroll
    for (int r = 0; r < 8; r++)
#pragma unroll
        for (int c = 0; c < 4; c++) acc2[r][c] = 0ull;

    for (int k0 = 0; k0 < DM; k0 += 32) {
#pragma unroll
        for (int j = 0; j < 8; j++) {
            int f = j * 128 + t;
            int row = f >> 3, kg = f & 7;
            float4 a4 = *(const float4*)(Ap + (size_t)row * DM + k0 + kg * 4);
            aT[kg*4+0][row] = a4.x; aT[kg*4+1][row] = a4.y;
            aT[kg*4+2][row] = a4.z; aT[kg*4+3][row] = a4.w;
        }
#pragma unroll
        for (int j = 0; j < 4; j++) {
            int f = j * 128 + t;
            int col = f >> 3, kg = f & 7;
            float4 b4 = *(const float4*)(Bp + (size_t)col * DM + k0 + kg * 4);
            bT[kg*4+0][col] = b4.x; bT[kg*4+1][col] = b4.y;
            bT[kg*4+2][col] = b4.z; bT[kg*4+3][col] = b4.w;
        }
        __syncthreads();
#pragma unroll 8
        for (int kk = 0; kk < 32; kk++) {
            float4 a0 = *(const float4*)&aT[kk][ty*8];
            float4 a1 = *(const float4*)&aT[kk][ty*8+4];
            ulonglong2 b01 = *(const ulonglong2*)&bT[kk][tx*8];
            ulonglong2 b23 = *(const ulonglong2*)&bT[kk][tx*8+4];
            float av[8] = {a0.x,a0.y,a0.z,a0.w,a1.x,a1.y,a1.z,a1.w};
#pragma unroll
            for (int r = 0; r < 8; r++) {
                u64 ap = bcast2(av[r]);
                acc2[r][0] = ffma2(acc2[r][0], ap, b01.x);
                acc2[r][1] = ffma2(acc2[r][1], ap, b01.y);
                acc2[r][2] = ffma2(acc2[r][2], ap, b23.x);
                acc2[r][3] = ffma2(acc2[r][3], ap, b23.y);
            }
        }
        __syncthreads();
    }
    float4 bi0 = *(const float4*)(bias + col0 + tx*8);
    float4 bi1 = *(const float4*)(bias + col0 + tx*8 + 4);
#pragma unroll
    for (int r = 0; r < 8; r++) {
        size_t row = row0 + ty*8 + r;
        float2 c0 = unpack2(acc2[r][0]), c1 = unpack2(acc2[r][1]);
        float2 c2 = unpack2(acc2[r][2]), c3 = unpack2(acc2[r][3]);
        *(float4*)(out + row * DM + col0 + tx*8) =
            make_float4(c0.x+bi0.x, c0.y+bi0.y, c1.x+bi0.z, c1.y+bi0.w);
        *(float4*)(out + row * DM + col0 + tx*8 + 4) =
            make_float4(c2.x+bi1.x, c2.y+bi1.y, c3.x+bi1.z, c3.y+bi1.w);
    }
}

// ============================================================
extern "C" void kernel_launch(void* const* d_in, const int* in_sizes, int n_in,
                              void* d_out, int out_size) {
    (void)in_sizes; (void)n_in; (void)out_size;
    const float* q    = (const float*)d_in[0];
    const float* k    = (const float*)d_in[1];
    const float* v    = (const float*)d_in[2];
    const float* mask = (const float*)d_in[3];
    const float* ow   = (const float*)d_in[4];
    const float* ob   = (const float*)d_in[5];
    float* out = (float*)d_out;

    cudaFuncSetAttribute(flash_kernel, cudaFuncAttributeMaxDynamicSharedMemorySize,
                         4 * 64 * 64 * (int)sizeof(float));

    rope_kernel<<<NB * NH * SEQ / 8, 256>>>(q, k);
    qt_gemm_kernel<<<dim3(SEQ / 128, NB * NH), 128>>>(mask);
    flash_kernel<<<dim3(SEQ / 64, NB * NH), 256, 4 * 64 * 64 * sizeof(float)>>>(v);
    out_gemm_kernel<<<dim3(NB * SEQ / 128, DM / 64), 128>>>(ow, ob, out);
}

// round 4
// speedup vs baseline: 1.4299x; 1.4027x over previous
#include <cuda_runtime.h>
#include <math.h>
#include <cstdint>

#define NB   2
#define NH   16
#define SEQ  2048
#define HD   64
#define DM   1024
#define SCALE 0.125f   // 64^-0.5

typedef unsigned long long u64;

// ================= packed f32x2 helpers =================
__device__ __forceinline__ u64 bcast2(float x) {
    u64 r; asm("mov.b64 %0, {%1, %1};" : "=l"(r) : "f"(x)); return r;
}
__device__ __forceinline__ u64 ffma2(u64 c, u64 a, u64 b) {
    u64 d; asm("fma.rn.f32x2 %0, %1, %2, %3;" : "=l"(d) : "l"(a), "l"(b), "l"(c)); return d;
}
__device__ __forceinline__ u64 fmul2(u64 a, u64 b) {
    u64 d; asm("mul.rn.f32x2 %0, %1, %2;" : "=l"(d) : "l"(a), "l"(b)); return d;
}
__device__ __forceinline__ float2 unpack2(u64 a) {
    float lo, hi; asm("mov.b64 {%0, %1}, %2;" : "=f"(lo), "=f"(hi) : "l"(a));
    return make_float2(lo, hi);
}

// ================= tf32 mma.sync helpers (portable PTX, sm_80+) =================
__device__ __forceinline__ uint32_t to_tf32(float x) {
    uint32_t u; asm("cvt.rna.tf32.f32 %0, %1;" : "=r"(u) : "f"(x));
    return u;
}
__device__ __forceinline__ void mma_tf32(float& c0, float& c1, float& c2, float& c3,
                                         uint32_t a0, uint32_t a1, uint32_t a2, uint32_t a3,
                                         uint32_t b0, uint32_t b1) {
    asm volatile("mma.sync.aligned.m16n8k8.row.col.f32.tf32.tf32.f32 "
                 "{%0,%1,%2,%3}, {%4,%5,%6,%7}, {%8,%9}, {%0,%1,%2,%3};"
                 : "+f"(c0), "+f"(c1), "+f"(c2), "+f"(c3)
                 : "r"(a0), "r"(a1), "r"(a2), "r"(a3), "r"(b0), "r"(b1));
}

// ---- scratch (device globals; no allocation APIs allowed) ----
__device__ float g_qr[NB*NH*SEQ*HD];   // 16 MB
__device__ float g_kr[NB*NH*SEQ*HD];   // 16 MB
__device__ float g_qt[NB*NH*SEQ*HD];   // 16 MB
__device__ float g_ctx[NB*SEQ*DM];     // 16 MB

// smem strides chosen so fragment LDS is bank-conflict-free:
//   A[r][c]: addr = r*36 + c  -> bank(4*(lane/4) + lane%4) all-distinct
//   B[k][n]: addr = k*72 + n  -> bank(8*(lane%4) + lane/4) all-distinct
#define ASTR 36
#define BSTR 72

// ============================================================
// 1) RoPE
// ============================================================
__global__ __launch_bounds__(256) void rope_kernel(const float* __restrict__ q,
                                                   const float* __restrict__ k) {
    int warp = threadIdx.x >> 5;
    int lane = threadIdx.x & 31;
    int row  = blockIdx.x * 8 + warp;
    int pos  = row & (SEQ - 1);
    float inv_freq = 1.0f / powf(10000.0f, (float)(2 * lane) * (1.0f / 64.0f));
    float sn, cs;
    sincosf((float)pos * inv_freq, &sn, &cs);
    size_t base = (size_t)row * HD;
    float a1 = q[base + lane], a2 = q[base + lane + 32];
    g_qr[base + lane]      = a1 * cs - a2 * sn;
    g_qr[base + lane + 32] = a2 * cs + a1 * sn;
    float b1 = k[base + lane], b2 = k[base + lane + 32];
    g_kr[base + lane]      = b1 * cs - b2 * sn;
    g_kr[base + lane + 32] = b2 * cs + b1 * sn;
}

// ============================================================
// Shared warp-MMA mainloop body: computes 32x64 per warp from
// As[128][ASTR], Bs[32][BSTR] (one 32-k chunk), accumulating acc[2][8][4].
// ============================================================
__device__ __forceinline__ void mma_chunk(const uint32_t* As, const uint32_t* Bs,
                                          int wrow, int lane, float acc[2][8][4]) {
    int g   = lane >> 2;       // groupID (0..7)
    int tig = lane & 3;        // threadID in group (0..3)
#pragma unroll
    for (int ks = 0; ks < 4; ks++) {
        int k0 = ks * 8;
        uint32_t a[2][4];
#pragma unroll
        for (int mt = 0; mt < 2; mt++) {
            int rb = wrow + mt * 16;
            a[mt][0] = As[(rb + g)     * ASTR + k0 + tig];
            a[mt][1] = As[(rb + 8 + g) * ASTR + k0 + tig];
            a[mt][2] = As[(rb + g)     * ASTR + k0 + tig + 4];
            a[mt][3] = As[(rb + 8 + g) * ASTR + k0 + tig + 4];
        }
#pragma unroll
        for (int nt = 0; nt < 8; nt++) {
            uint32_t b0 = Bs[(k0 + tig)     * BSTR + nt * 8 + g];
            uint32_t b1 = Bs[(k0 + tig + 4) * BSTR + nt * 8 + g];
            mma_tf32(acc[0][nt][0], acc[0][nt][1], acc[0][nt][2], acc[0][nt][3],
                     a[0][0], a[0][1], a[0][2], a[0][3], b0, b1);
            mma_tf32(acc[1][nt][0], acc[1][nt][1], acc[1][nt][2], acc[1][nt][3],
                     a[1][0], a[1][1], a[1][2], a[1][3], b0, b1);
        }
    }
}

// Stage A[128 rows][32 k] (K-major gmem, stride ld) -> As (tf32)
__device__ __forceinline__ void stage_A(uint32_t* As, const float* gp, int ld, int t) {
#pragma unroll
    for (int j = 0; j < 8; j++) {
        int idx = j * 128 + t;
        int row = idx >> 3, kg = idx & 7;
        float4 a = *(const float4*)(gp + (size_t)row * ld + kg * 4);
        uint32_t* d = As + row * ASTR + kg * 4;
        d[0] = to_tf32(a.x); d[1] = to_tf32(a.y); d[2] = to_tf32(a.z); d[3] = to_tf32(a.w);
    }
}

// ============================================================
// 2) qt[b,h] = W[h] @ qr[b,h]  via mma.sync tf32
// ============================================================
__global__ __launch_bounds__(128) void qt_mma_kernel(const float* __restrict__ mask) {
    __shared__ uint32_t As[128 * ASTR];
    __shared__ uint32_t Bs[32 * BSTR];
    int t = threadIdx.x, w = t >> 5, lane = t & 31;
    int bh = blockIdx.y, h = bh & (NH - 1);
    int row0 = blockIdx.x * 128;
    const float* Ap = mask + (size_t)h * SEQ * SEQ + (size_t)row0 * SEQ;
    const float* Bq = g_qr + (size_t)bh * SEQ * HD;

    float acc[2][8][4];
#pragma unroll
    for (int mt = 0; mt < 2; mt++)
#pragma unroll
        for (int nt = 0; nt < 8; nt++)
#pragma unroll
            for (int e = 0; e < 4; e++) acc[mt][nt][e] = 0.f;

    for (int k0 = 0; k0 < SEQ; k0 += 32) {
        stage_A(As, Ap + k0, SEQ, t);
        // B[k][n] = qr[(k0+k)*HD + n], straight copy (4 float4 per thread)
#pragma unroll
        for (int j = 0; j < 4; j++) {
            int idx = j * 128 + t;
            int k = idx >> 4, ng = idx & 15;
            float4 a = *(const float4*)(Bq + (size_t)(k0 + k) * HD + ng * 4);
            uint32_t* d = Bs + k * BSTR + ng * 4;
            d[0] = to_tf32(a.x); d[1] = to_tf32(a.y); d[2] = to_tf32(a.z); d[3] = to_tf32(a.w);
        }
        __syncthreads();
        mma_chunk(As, Bs, w * 32, lane, acc);
        __syncthreads();
    }

    int g = lane >> 2, tig = lane & 3;
    float* op = g_qt + ((size_t)bh * SEQ + row0 + w * 32) * HD;
#pragma unroll
    for (int mt = 0; mt < 2; mt++)
#pragma unroll
        for (int nt = 0; nt < 8; nt++) {
            int col = nt * 8 + 2 * tig;
            int r0 = mt * 16 + g;
            *(float2*)(op + (size_t)r0 * HD + col)       = make_float2(acc[mt][nt][0], acc[mt][nt][1]);
            *(float2*)(op + (size_t)(r0 + 8) * HD + col) = make_float2(acc[mt][nt][2], acc[mt][nt][3]);
        }
}

// ============================================================
// 3) Flash attention (SIMT f32x2, unchanged)
// ============================================================
__global__ __launch_bounds__(256) void flash_kernel(const float* __restrict__ v) {
    extern __shared__ float sm[];
    float* qS = sm;
    float* kS = sm + 64*64;
    float* vS = sm + 2*64*64;
    float* pS = sm + 3*64*64;

    int t  = threadIdx.x;
    int ty = t >> 4;
    int tx = t & 15;
    int bh = blockIdx.y;
    int b  = bh >> 4, h = bh & 15;
    int q0 = blockIdx.x * 64;

    const float* qtp = g_qt + ((size_t)bh * SEQ + q0) * HD;
    const float* kp  = g_kr + (size_t)bh * SEQ * HD;
    const float* vp  = v    + (size_t)bh * SEQ * HD;

#pragma unroll
    for (int j = 0; j < 4; j++) {
        int f = j * 256 + t;
        int row = f >> 4, dg = f & 15;
        float4 qv = *(const float4*)(qtp + (size_t)row * HD + dg * 4);
        qv.x *= SCALE; qv.y *= SCALE; qv.z *= SCALE; qv.w *= SCALE;
        *(float4*)&qS[row*64 + dg*4] = qv;
    }

    float m[4], l[4];
    u64 o2[4][2];
#pragma unroll
    for (int r = 0; r < 4; r++) {
        m[r] = -1e30f; l[r] = 0.f;
        o2[r][0] = 0ull; o2[r][1] = 0ull;
    }

    int swz = 4 * (tx & 7);
    for (int kt = 0; kt < SEQ / 64; kt++) {
        int k0 = kt * 64;
#pragma unroll
        for (int j = 0; j < 4; j++) {
            int f = j * 256 + t;
            int row = f >> 4, dg = f & 15;
            float4 kv = *(const float4*)(kp + (size_t)(k0 + row) * HD + dg * 4);
            int dsw = (dg * 4) ^ (4 * ((row >> 2) & 7));
            *(float4*)&kS[row*64 + dsw]  = kv;
            *(float4*)&vS[row*64 + dg*4] = *(const float4*)(vp + (size_t)(k0 + row) * HD + dg * 4);
        }
        __syncthreads();

        u64 s2[4][4];
#pragma unroll
        for (int r = 0; r < 4; r++)
#pragma unroll
            for (int c = 0; c < 4; c++) s2[r][c] = 0ull;
#pragma unroll 4
        for (int dd = 0; dd < 64; dd += 4) {
            ulonglong2 qv[4], kv[4];
#pragma unroll
            for (int r = 0; r < 4; r++) qv[r] = *(const ulonglong2*)&qS[(ty*4+r)*64 + dd];
#pragma unroll
            for (int c = 0; c < 4; c++) kv[c] = *(const ulonglong2*)&kS[(tx*4+c)*64 + (dd ^ swz)];
#pragma unroll
            for (int r = 0; r < 4; r++)
#pragma unroll
                for (int c = 0; c < 4; c++) {
                    s2[r][c] = ffma2(s2[r][c], qv[r].x, kv[c].x);
                    s2[r][c] = ffma2(s2[r][c], qv[r].y, kv[c].y);
                }
        }
        float s[4][4];
#pragma unroll
        for (int r = 0; r < 4; r++)
#pragma unroll
            for (int c = 0; c < 4; c++) {
                float2 f2 = unpack2(s2[r][c]);
                s[r][c] = f2.x + f2.y;
            }

#pragma unroll
        for (int r = 0; r < 4; r++) {
            float rm = fmaxf(fmaxf(s[r][0], s[r][1]), fmaxf(s[r][2], s[r][3]));
#pragma unroll
            for (int o = 1; o < 16; o <<= 1)
                rm = fmaxf(rm, __shfl_xor_sync(0xffffffffu, rm, o));
            float mn   = fmaxf(m[r], rm);
            float corr = __expf(m[r] - mn);
            float rs = 0.f;
#pragma unroll
            for (int c = 0; c < 4; c++) {
                float p = __expf(s[r][c] - mn);
                s[r][c] = p; rs += p;
            }
#pragma unroll
            for (int o = 1; o < 16; o <<= 1)
                rs += __shfl_xor_sync(0xffffffffu, rs, o);
            l[r] = l[r] * corr + rs;
            m[r] = mn;
            u64 cp = bcast2(corr);
            o2[r][0] = fmul2(o2[r][0], cp);
            o2[r][1] = fmul2(o2[r][1], cp);
        }
#pragma unroll
        for (int r = 0; r < 4; r++)
            *(float4*)&pS[(ty*4+r)*64 + tx*4] = make_float4(s[r][0], s[r][1], s[r][2], s[r][3]);
        __syncthreads();

#pragma unroll 8
        for (int kk = 0; kk < 64; kk++) {
            ulonglong2 vv = *(const ulonglong2*)&vS[kk*64 + tx*4];
            u64 p0 = bcast2(pS[(ty*4+0)*64 + kk]);
            u64 p1 = bcast2(pS[(ty*4+1)*64 + kk]);
            u64 p2 = bcast2(pS[(ty*4+2)*64 + kk]);
            u64 p3 = bcast2(pS[(ty*4+3)*64 + kk]);
            o2[0][0] = ffma2(o2[0][0], p0, vv.x); o2[0][1] = ffma2(o2[0][1], p0, vv.y);
            o2[1][0] = ffma2(o2[1][0], p1, vv.x); o2[1][1] = ffma2(o2[1][1], p1, vv.y);
            o2[2][0] = ffma2(o2[2][0], p2, vv.x); o2[2][1] = ffma2(o2[2][1], p2, vv.y);
            o2[3][0] = ffma2(o2[3][0], p3, vv.x); o2[3][1] = ffma2(o2[3][1], p3, vv.y);
        }
        __syncthreads();
    }

    float* cp = g_ctx + ((size_t)b * SEQ + q0) * DM + h * HD;
#pragma unroll
    for (int r = 0; r < 4; r++) {
        float invl = 1.0f / l[r];
        float2 a0 = unpack2(o2[r][0]), a1 = unpack2(o2[r][1]);
        *(float4*)(cp + (size_t)(ty*4 + r) * DM + tx*4) =
            make_float4(a0.x*invl, a0.y*invl, a1.x*invl, a1.y*invl);
    }
}

// ============================================================
// 4) out = ctx @ out_w^T + out_b  via mma.sync tf32
// ============================================================
__global__ __launch_bounds__(128) void out_mma_kernel(const float* __restrict__ wgt,
                                                      const float* __restrict__ bias,
                                                      float* __restrict__ out) {
    __shared__ uint32_t As[128 * ASTR];
    __shared__ uint32_t Bs[32 * BSTR];
    int t = threadIdx.x, w = t >> 5, lane = t & 31;
    int row0 = blockIdx.x * 128;
    int col0 = blockIdx.y * 64;
    const float* Ap = g_ctx + (size_t)row0 * DM;
    const float* Bp = wgt   + (size_t)col0 * DM;

    float acc[2][8][4];
#pragma unroll
    for (int mt = 0; mt < 2; mt++)
#pragma unroll
        for (int nt = 0; nt < 8; nt++)
#pragma unroll
            for (int e = 0; e < 4; e++) acc[mt][nt][e] = 0.f;

    for (int k0 = 0; k0 < DM; k0 += 32) {
        stage_A(As, Ap + k0, DM, t);
        // B[k][n] = w[(col0+n)][k0+k]  (transpose during staging)
#pragma unroll
        for (int j = 0; j < 4; j++) {
            int idx = j * 128 + t;
            int n = idx >> 3, kg = idx & 7;
            float4 a = *(const float4*)(Bp + (size_t)n * DM + k0 + kg * 4);
            Bs[(kg*4+0) * BSTR + n] = to_tf32(a.x);
            Bs[(kg*4+1) * BSTR + n] = to_tf32(a.y);
            Bs[(kg*4+2) * BSTR + n] = to_tf32(a.z);
            Bs[(kg*4+3) * BSTR + n] = to_tf32(a.w);
        }
        __syncthreads();
        mma_chunk(As, Bs, w * 32, lane, acc);
        __syncthreads();
    }

    int g = lane >> 2, tig = lane & 3;
#pragma unroll
    for (int mt = 0; mt < 2; mt++)
#pragma unroll
        for (int nt = 0; nt < 8; nt++) {
            int col = col0 + nt * 8 + 2 * tig;
            size_t r0 = row0 + w * 32 + mt * 16 + g;
            float2 bi = *(const float2*)(bias + col);
            *(float2*)(out + r0 * DM + col) =
                make_float2(acc[mt][nt][0] + bi.x, acc[mt][nt][1] + bi.y);
            *(float2*)(out + (r0 + 8) * DM + col) =
                make_float2(acc[mt][nt][2] + bi.x, acc[mt][nt][3] + bi.y);
        }
}

// ============================================================
extern "C" void kernel_launch(void* const* d_in, const int* in_sizes, int n_in,
                              void* d_out, int out_size) {
    (void)in_sizes; (void)n_in; (void)out_size;
    const float* q    = (const float*)d_in[0];
    const float* k    = (const float*)d_in[1];
    const float* v    = (const float*)d_in[2];
    const float* mask = (const float*)d_in[3];
    const float* ow   = (const float*)d_in[4];
    const float* ob   = (const float*)d_in[5];
    float* out = (float*)d_out;

    cudaFuncSetAttribute(flash_kernel, cudaFuncAttributeMaxDynamicSharedMemorySize,
                         4 * 64 * 64 * (int)sizeof(float));

    rope_kernel<<<NB * NH * SEQ / 8, 256>>>(q, k);
    qt_mma_kernel<<<dim3(SEQ / 128, NB * NH), 128>>>(mask);
    flash_kernel<<<dim3(SEQ / 64, NB * NH), 256, 4 * 64 * 64 * sizeof(float)>>>(v);
    out_mma_kernel<<<dim3(NB * SEQ / 128, DM / 64), 128>>>(ow, ob, out);
}

// round 5
// speedup vs baseline: 2.0727x; 1.4495x over previous
#include <cuda_runtime.h>
#include <cuda_bf16.h>
#include <math.h>
#include <cstdint>

#define NB   2
#define NH   16
#define BH   (NB*NH)
#define SEQ  2048
#define HD   64
#define DM   1024
#define SCALE 0.125f   // 64^-0.5

// ---- scratch (device globals; no allocation APIs allowed) ----
__device__ uint32_t g_qrT_hi[BH*HD*(SEQ/2)];  // 8 MB: rope(q)^T, bf16-hi pairs along seq
__device__ uint32_t g_qrT_lo[BH*HD*(SEQ/2)];  // 8 MB
__device__ uint32_t g_vt_hi [BH*HD*(SEQ/2)];  // 8 MB: v^T, bf16-hi pairs along seq
__device__ uint32_t g_vt_lo [BH*HD*(SEQ/2)];  // 8 MB
__device__ float    g_kr [BH*SEQ*HD];         // 16 MB: rope(k), fp32
__device__ float    g_qt [BH*SEQ*HD];         // 16 MB: W @ rope(q)
__device__ float    g_ctx[NB*SEQ*DM];         // 16 MB: attention output (b, s, h*d)

// ================= split-bf16 helpers =================
// pack (x,y) -> bf16x2 hi word + bf16x2 residual word
__device__ __forceinline__ void split2(float x, float y, uint32_t& hi, uint32_t& lo) {
    uint32_t h;
    asm("cvt.rn.bf16x2.f32 %0, %1, %2;" : "=r"(h) : "f"(y), "f"(x));  // low<-x, high<-y
    float hx = __uint_as_float(h << 16);
    float hy = __uint_as_float(h & 0xFFFF0000u);
    asm("cvt.rn.bf16x2.f32 %0, %1, %2;" : "=r"(lo) : "f"(y - hy), "f"(x - hx));
    hi = h;
}
__device__ __forceinline__ void split4(float4 a, uint32_t* h2, uint32_t* l2) {
    split2(a.x, a.y, h2[0], l2[0]);
    split2(a.z, a.w, h2[1], l2[1]);
}

__device__ __forceinline__ void mma_bf16(float* c,
        uint32_t a0, uint32_t a1, uint32_t a2, uint32_t a3, uint32_t b0, uint32_t b1) {
    asm volatile("mma.sync.aligned.m16n8k16.row.col.f32.bf16.bf16.f32 "
                 "{%0,%1,%2,%3}, {%4,%5,%6,%7}, {%8,%9}, {%0,%1,%2,%3};"
                 : "+f"(c[0]), "+f"(c[1]), "+f"(c[2]), "+f"(c[3])
                 : "r"(a0), "r"(a1), "r"(a2), "r"(a3), "r"(b0), "r"(b1));
}
// split-bf16 product: hh + hl + lh  (ll dropped, ~2^-16 effective precision)
__device__ __forceinline__ void mma3(float* c, const uint32_t* ah, const uint32_t* al,
                                     uint32_t bh0, uint32_t bh1, uint32_t bl0, uint32_t bl1) {
    mma_bf16(c, ah[0], ah[1], ah[2], ah[3], bh0, bh1);
    mma_bf16(c, ah[0], ah[1], ah[2], ah[3], bl0, bl1);
    mma_bf16(c, al[0], al[1], al[2], al[3], bh0, bh1);
}

// ============================================================
// 1) RoPE: writes g_kr (fp32, natural) + g_qrT (bf16 hi/lo, d-major pairs-along-seq)
//    block = (32 seq rows x 64 d) of one (b,h)
// ============================================================
__global__ __launch_bounds__(256) void rope_kernel(const float* __restrict__ q,
                                                   const float* __restrict__ k) {
    __shared__ float qs[64][33];   // [d][s_local], rotated q
    int t = threadIdx.x;
    int bh = blockIdx.y;
    int s0 = blockIdx.x * 32;
    int d  = t & 31;               // constant per thread across j-loop
    float inv_freq = 1.0f / powf(10000.0f, (float)(2 * d) * (1.0f / 64.0f));
#pragma unroll
    for (int j = 0; j < 4; j++) {
        int idx = j * 256 + t;
        int sl = idx >> 5;
        int s = s0 + sl;
        float sn, cs;
        sincosf((float)s * inv_freq, &sn, &cs);
        size_t base = ((size_t)bh * SEQ + s) * HD;
        float a1 = q[base + d], a2 = q[base + d + 32];
        qs[d][sl]      = a1 * cs - a2 * sn;
        qs[d + 32][sl] = a2 * cs + a1 * sn;
        float b1 = k[base + d], b2 = k[base + d + 32];
        g_kr[base + d]      = b1 * cs - b2 * sn;
        g_kr[base + d + 32] = b2 * cs + b1 * sn;
    }
    __syncthreads();
    // transpose out: 64 d x 16 seq-pairs
#pragma unroll
    for (int j = 0; j < 4; j++) {
        int idx = j * 256 + t;
        int dd = idx >> 4, sp = idx & 15;
        uint32_t hi, lo;
        split2(qs[dd][2 * sp], qs[dd][2 * sp + 1], hi, lo);
        size_t o = ((size_t)bh * HD + dd) * (SEQ / 2) + s0 / 2 + sp;
        g_qrT_hi[o] = hi; g_qrT_lo[o] = lo;
    }
}

// ============================================================
// 1b) V transpose: g_vt[d][seq-pairs] bf16 hi/lo
// ============================================================
__global__ __launch_bounds__(256) void vT_kernel(const float* __restrict__ v) {
    __shared__ float vs[64][65];   // [s_local][d]
    int t = threadIdx.x;
    int bh = blockIdx.y;
    int s0 = blockIdx.x * 64;
#pragma unroll
    for (int j = 0; j < 16; j++) {
        int idx = j * 256 + t;
        int sl = idx >> 6, d = idx & 63;
        vs[sl][d] = v[((size_t)bh * SEQ + s0 + sl) * HD + d];
    }
    __syncthreads();
#pragma unroll
    for (int j = 0; j < 8; j++) {
        int idx = j * 256 + t;
        int d = idx >> 5, sp = idx & 31;
        uint32_t hi, lo;
        split2(vs[2 * sp][d], vs[2 * sp + 1][d], hi, lo);
        size_t o = ((size_t)bh * HD + d) * (SEQ / 2) + s0 / 2 + sp;
        g_vt_hi[o] = hi; g_vt_lo[o] = lo;
    }
}

// ============================================================
// 2) qt[b,h] = W[h] @ qr[b,h]  -- split-bf16 3-mma warp GEMM
//    block tile 128x64, Kc=32, 4 warps (each 32 rows x 64 cols)
// ============================================================
#define GSTR 20
__global__ __launch_bounds__(128) void qt_mma_kernel(const float* __restrict__ mask) {
    __shared__ uint32_t Ah[128 * GSTR], Al[128 * GSTR];
    __shared__ uint32_t Bh[64 * GSTR],  Bl[64 * GSTR];
    int t = threadIdx.x, w = t >> 5, lane = t & 31;
    int g = lane >> 2, tig = lane & 3;
    int bh = blockIdx.y, h = bh & (NH - 1);
    int row0 = blockIdx.x * 128;
    const float* Ap = mask + (size_t)h * SEQ * SEQ + (size_t)row0 * SEQ;
    const uint32_t* Bph = g_qrT_hi + (size_t)bh * HD * (SEQ / 2);
    const uint32_t* Bpl = g_qrT_lo + (size_t)bh * HD * (SEQ / 2);

    float acc[2][8][4];
#pragma unroll
    for (int mt = 0; mt < 2; mt++)
#pragma unroll
        for (int nt = 0; nt < 8; nt++)
#pragma unroll
            for (int e = 0; e < 4; e++) acc[mt][nt][e] = 0.f;

    for (int c = 0; c < SEQ / 32; c++) {
        int k0 = c * 32;
#pragma unroll
        for (int j = 0; j < 8; j++) {           // A: 128 rows x 32 k fp32 -> split
            int idx = j * 128 + t;
            int row = idx >> 3, kg = idx & 7;
            float4 a = *(const float4*)(Ap + (size_t)row * SEQ + k0 + kg * 4);
            uint32_t h2[2], l2[2]; split4(a, h2, l2);
            Ah[row * GSTR + kg * 2] = h2[0]; Ah[row * GSTR + kg * 2 + 1] = h2[1];
            Al[row * GSTR + kg * 2] = l2[0]; Al[row * GSTR + kg * 2 + 1] = l2[1];
        }
#pragma unroll
        for (int j = 0; j < 8; j++) {           // B: copy pre-split words
            int idx = j * 128 + t;
            int d = idx >> 4, wd = idx & 15;
            size_t o = (size_t)d * (SEQ / 2) + k0 / 2 + wd;
            Bh[d * GSTR + wd] = Bph[o];
            Bl[d * GSTR + wd] = Bpl[o];
        }
        __syncthreads();
#pragma unroll
        for (int ks = 0; ks < 2; ks++) {
            uint32_t ah[2][4], al[2][4];
#pragma unroll
            for (int mt = 0; mt < 2; mt++) {
                int rb = w * 32 + mt * 16;
                int ra  = (rb + g) * GSTR + ks * 8 + tig;
                int ra8 = (rb + 8 + g) * GSTR + ks * 8 + tig;
                ah[mt][0] = Ah[ra]; ah[mt][1] = Ah[ra8]; ah[mt][2] = Ah[ra + 4]; ah[mt][3] = Ah[ra8 + 4];
                al[mt][0] = Al[ra]; al[mt][1] = Al[ra8]; al[mt][2] = Al[ra + 4]; al[mt][3] = Al[ra8 + 4];
            }
#pragma unroll
            for (int nt = 0; nt < 8; nt++) {
                int rbk = (nt * 8 + g) * GSTR + ks * 8 + tig;
                uint32_t bh0 = Bh[rbk], bh1 = Bh[rbk + 4];
                uint32_t bl0 = Bl[rbk], bl1 = Bl[rbk + 4];
                mma3(acc[0][nt], ah[0], al[0], bh0, bh1, bl0, bl1);
                mma3(acc[1][nt], ah[1], al[1], bh0, bh1, bl0, bl1);
            }
        }
        __syncthreads();
    }
    float* op = g_qt + ((size_t)bh * SEQ + row0) * HD;
#pragma unroll
    for (int mt = 0; mt < 2; mt++)
#pragma unroll
        for (int nt = 0; nt < 8; nt++) {
            int r0 = w * 32 + mt * 16 + g;
            int col = nt * 8 + 2 * tig;
            *(float2*)(op + (size_t)r0 * HD + col)       = make_float2(acc[mt][nt][0], acc[mt][nt][1]);
            *(float2*)(op + (size_t)(r0 + 8) * HD + col) = make_float2(acc[mt][nt][2], acc[mt][nt][3]);
        }
}

// ============================================================
// 3) Flash attention -- split-bf16 tensor-core FA2
//    CTA: 128 q-rows x full seq, BN=64 keys/iter, 8 warps (16 rows each)
// ============================================================
#define FSTR 36
#define FQ_H 0
#define FQ_L (FQ_H + 128*FSTR)
#define FK_H (FQ_L + 128*FSTR)
#define FK_L (FK_H + 64*FSTR)
#define FV_H (FK_L + 64*FSTR)
#define FV_L (FV_H + 64*FSTR)
#define FLASH_SMEM_WORDS (FV_L + 64*FSTR)   // 18432 words = 73728 B

__global__ __launch_bounds__(256, 2) void flash_kernel() {
    extern __shared__ uint32_t fsm[];
    uint32_t* Qh = fsm + FQ_H; uint32_t* Ql = fsm + FQ_L;
    uint32_t* Kh = fsm + FK_H; uint32_t* Kl = fsm + FK_L;
    uint32_t* Vh = fsm + FV_H; uint32_t* Vl = fsm + FV_L;

    int t = threadIdx.x, w = t >> 5, lane = t & 31;
    int g = lane >> 2, tig = lane & 3;
    int bh = blockIdx.y;
    int b = bh >> 4, h = bh & 15;
    int q0 = blockIdx.x * 128;
    int rb = w * 16;

    const float*    qtp = g_qt + ((size_t)bh * SEQ + q0) * HD;
    const float*    kp  = g_kr + (size_t)bh * SEQ * HD;
    const uint32_t* vph = g_vt_hi + (size_t)bh * HD * (SEQ / 2);
    const uint32_t* vpl = g_vt_lo + (size_t)bh * HD * (SEQ / 2);

    // stage Q (scaled, split) once: 128 rows x 64 d
#pragma unroll
    for (int j = 0; j < 8; j++) {
        int idx = j * 256 + t;
        int row = idx >> 4, dg = idx & 15;
        float4 a = *(const float4*)(qtp + (size_t)row * HD + dg * 4);
        a.x *= SCALE; a.y *= SCALE; a.z *= SCALE; a.w *= SCALE;
        uint32_t h2[2], l2[2]; split4(a, h2, l2);
        Qh[row * FSTR + dg * 2] = h2[0]; Qh[row * FSTR + dg * 2 + 1] = h2[1];
        Ql[row * FSTR + dg * 2] = l2[0]; Ql[row * FSTR + dg * 2 + 1] = l2[1];
    }

    float m0 = -1e30f, m1 = -1e30f, l0 = 0.f, l1 = 0.f;
    float ctx[8][4];
#pragma unroll
    for (int nt = 0; nt < 8; nt++)
#pragma unroll
        for (int e = 0; e < 4; e++) ctx[nt][e] = 0.f;

    for (int kt = 0; kt < SEQ / 64; kt++) {
        __syncthreads();
        // stage K tile (64 keys x 64 d), fp32 -> split
#pragma unroll
        for (int j = 0; j < 4; j++) {
            int idx = j * 256 + t;
            int row = idx >> 4, dg = idx & 15;
            float4 a = *(const float4*)(kp + (size_t)(kt * 64 + row) * HD + dg * 4);
            uint32_t h2[2], l2[2]; split4(a, h2, l2);
            Kh[row * FSTR + dg * 2] = h2[0]; Kh[row * FSTR + dg * 2 + 1] = h2[1];
            Kl[row * FSTR + dg * 2] = l2[0]; Kl[row * FSTR + dg * 2 + 1] = l2[1];
        }
        // stage V tile: copy pre-split words (64 d x 32 key-pairs)
#pragma unroll
        for (int j = 0; j < 8; j++) {
            int idx = j * 256 + t;
            int d = idx >> 5, wd = idx & 31;
            size_t o = (size_t)d * (SEQ / 2) + kt * 32 + wd;
            Vh[d * FSTR + wd] = vph[o];
            Vl[d * FSTR + wd] = vpl[o];
        }
        __syncthreads();

        // S = Qs @ K^T : per-warp 16x64
        float s[8][4];
#pragma unroll
        for (int nt = 0; nt < 8; nt++)
#pragma unroll
            for (int e = 0; e < 4; e++) s[nt][e] = 0.f;
#pragma unroll
        for (int ks = 0; ks < 4; ks++) {
            int ra  = (rb + g) * FSTR + ks * 8 + tig;
            int ra8 = (rb + 8 + g) * FSTR + ks * 8 + tig;
            uint32_t qh[4] = {Qh[ra], Qh[ra8], Qh[ra + 4], Qh[ra8 + 4]};
            uint32_t ql[4] = {Ql[ra], Ql[ra8], Ql[ra + 4], Ql[ra8 + 4]};
#pragma unroll
            for (int nt = 0; nt < 8; nt++) {
                int rk = (nt * 8 + g) * FSTR + ks * 8 + tig;
                mma3(s[nt], qh, ql, Kh[rk], Kh[rk + 4], Kl[rk], Kl[rk + 4]);
            }
        }

        // online softmax: thread owns rows (rb+g) and (rb+8+g), cols 2tig(+1) per ntile
        float rm0 = -1e30f, rm1 = -1e30f;
#pragma unroll
        for (int nt = 0; nt < 8; nt++) {
            rm0 = fmaxf(rm0, fmaxf(s[nt][0], s[nt][1]));
            rm1 = fmaxf(rm1, fmaxf(s[nt][2], s[nt][3]));
        }
        rm0 = fmaxf(rm0, __shfl_xor_sync(0xffffffffu, rm0, 1));
        rm0 = fmaxf(rm0, __shfl_xor_sync(0xffffffffu, rm0, 2));
        rm1 = fmaxf(rm1, __shfl_xor_sync(0xffffffffu, rm1, 1));
        rm1 = fmaxf(rm1, __shfl_xor_sync(0xffffffffu, rm1, 2));
        float mn0 = fmaxf(m0, rm0), mn1 = fmaxf(m1, rm1);
        float corr0 = __expf(m0 - mn0), corr1 = __expf(m1 - mn1);
        m0 = mn0; m1 = mn1;
        float rs0 = 0.f, rs1 = 0.f;
#pragma unroll
        for (int nt = 0; nt < 8; nt++) {
            s[nt][0] = __expf(s[nt][0] - mn0); rs0 += s[nt][0];
            s[nt][1] = __expf(s[nt][1] - mn0); rs0 += s[nt][1];
            s[nt][2] = __expf(s[nt][2] - mn1); rs1 += s[nt][2];
            s[nt][3] = __expf(s[nt][3] - mn1); rs1 += s[nt][3];
        }
        rs0 += __shfl_xor_sync(0xffffffffu, rs0, 1);
        rs0 += __shfl_xor_sync(0xffffffffu, rs0, 2);
        rs1 += __shfl_xor_sync(0xffffffffu, rs1, 1);
        rs1 += __shfl_xor_sync(0xffffffffu, rs1, 2);
        l0 = l0 * corr0 + rs0;
        l1 = l1 * corr1 + rs1;
#pragma unroll
        for (int nt = 0; nt < 8; nt++) {
            ctx[nt][0] *= corr0; ctx[nt][1] *= corr0;
            ctx[nt][2] *= corr1; ctx[nt][3] *= corr1;
        }

        // ctx += P @ V : P fragments built directly from S fragments (C->A layout identity)
#pragma unroll
        for (int ks = 0; ks < 4; ks++) {
            uint32_t ph[4], pl[4];
            split2(s[2 * ks][0],     s[2 * ks][1],     ph[0], pl[0]);
            split2(s[2 * ks][2],     s[2 * ks][3],     ph[1], pl[1]);
            split2(s[2 * ks + 1][0], s[2 * ks + 1][1], ph[2], pl[2]);
            split2(s[2 * ks + 1][2], s[2 * ks + 1][3], ph[3], pl[3]);
#pragma unroll
            for (int nt = 0; nt < 8; nt++) {
                int rv = (nt * 8 + g) * FSTR + ks * 8 + tig;
                mma3(ctx[nt], ph, pl, Vh[rv], Vh[rv + 4], Vl[rv], Vl[rv + 4]);
            }
        }
    }

    float invl0 = 1.0f / l0, invl1 = 1.0f / l1;
    int r0 = q0 + rb + g;
#pragma unroll
    for (int nt = 0; nt < 8; nt++) {
        int col = h * HD + nt * 8 + 2 * tig;
        *(float2*)(g_ctx + ((size_t)b * SEQ + r0) * DM + col) =
            make_float2(ctx[nt][0] * invl0, ctx[nt][1] * invl0);
        *(float2*)(g_ctx + ((size_t)b * SEQ + r0 + 8) * DM + col) =
            make_float2(ctx[nt][2] * invl1, ctx[nt][3] * invl1);
    }
}

// ============================================================
// 4) out = ctx @ out_w^T + out_b  -- split-bf16 3-mma warp GEMM
// ============================================================
__global__ __launch_bounds__(128) void out_mma_kernel(const float* __restrict__ wgt,
                                                      const float* __restrict__ bias,
                                                      float* __restrict__ out) {
    __shared__ uint32_t Ah[128 * GSTR], Al[128 * GSTR];
    __shared__ uint32_t Bh[64 * GSTR],  Bl[64 * GSTR];
    int t = threadIdx.x, w = t >> 5, lane = t & 31;
    int g = lane >> 2, tig = lane & 3;
    int row0 = blockIdx.x * 128;
    int col0 = blockIdx.y * 64;
    const float* Ap = g_ctx + (size_t)row0 * DM;
    const float* Bp = wgt   + (size_t)col0 * DM;

    float acc[2][8][4];
#pragma unroll
    for (int mt = 0; mt < 2; mt++)
#pragma unroll
        for (int nt = 0; nt < 8; nt++)
#pragma unroll
            for (int e = 0; e < 4; e++) acc[mt][nt][e] = 0.f;

    for (int c = 0; c < DM / 32; c++) {
        int k0 = c * 32;
#pragma unroll
        for (int j = 0; j < 8; j++) {
            int idx = j * 128 + t;
            int row = idx >> 3, kg = idx & 7;
            float4 a = *(const float4*)(Ap + (size_t)row * DM + k0 + kg * 4);
            uint32_t h2[2], l2[2]; split4(a, h2, l2);
            Ah[row * GSTR + kg * 2] = h2[0]; Ah[row * GSTR + kg * 2 + 1] = h2[1];
            Al[row * GSTR + kg * 2] = l2[0]; Al[row * GSTR + kg * 2 + 1] = l2[1];
        }
#pragma unroll
        for (int j = 0; j < 4; j++) {
            int idx = j * 128 + t;
            int n = idx >> 3, kg = idx & 7;
            float4 a = *(const float4*)(Bp + (size_t)n * DM + k0 + kg * 4);
            uint32_t h2[2], l2[2]; split4(a, h2, l2);
            Bh[n * GSTR + kg * 2] = h2[0]; Bh[n * GSTR + kg * 2 + 1] = h2[1];
            Bl[n * GSTR + kg * 2] = l2[0]; Bl[n * GSTR + kg * 2 + 1] = l2[1];
        }
        __syncthreads();
#pragma unroll
        for (int ks = 0; ks < 2; ks++) {
            uint32_t ah[2][4], al[2][4];
#pragma unroll
            for (int mt = 0; mt < 2; mt++) {
                int rb = w * 32 + mt * 16;
                int ra  = (rb + g) * GSTR + ks * 8 + tig;
                int ra8 = (rb + 8 + g) * GSTR + ks * 8 + tig;
                ah[mt][0] = Ah[ra]; ah[mt][1] = Ah[ra8]; ah[mt][2] = Ah[ra + 4]; ah[mt][3] = Ah[ra8 + 4];
                al[mt][0] = Al[ra]; al[mt][1] = Al[ra8]; al[mt][2] = Al[ra + 4]; al[mt][3] = Al[ra8 + 4];
            }
#pragma unroll
            for (int nt = 0; nt < 8; nt++) {
                int rbk = (nt * 8 + g) * GSTR + ks * 8 + tig;
                uint32_t bh0 = Bh[rbk], bh1 = Bh[rbk + 4];
                uint32_t bl0 = Bl[rbk], bl1 = Bl[rbk + 4];
                mma3(acc[0][nt], ah[0], al[0], bh0, bh1, bl0, bl1);
                mma3(acc[1][nt], ah[1], al[1], bh0, bh1, bl0, bl1);
            }
        }
        __syncthreads();
    }
#pragma unroll
    for (int mt = 0; mt < 2; mt++)
#pragma unroll
        for (int nt = 0; nt < 8; nt++) {
            int col = col0 + nt * 8 + 2 * tig;
            size_t r0 = row0 + w * 32 + mt * 16 + g;
            float2 bi = *(const float2*)(bias + col);
            *(float2*)(out + r0 * DM + col) =
                make_float2(acc[mt][nt][0] + bi.x, acc[mt][nt][1] + bi.y);
            *(float2*)(out + (r0 + 8) * DM + col) =
                make_float2(acc[mt][nt][2] + bi.x, acc[mt][nt][3] + bi.y);
        }
}

// ============================================================
extern "C" void kernel_launch(void* const* d_in, const int* in_sizes, int n_in,
                              void* d_out, int out_size) {
    (void)in_sizes; (void)n_in; (void)out_size;
    const float* q    = (const float*)d_in[0];
    const float* k    = (const float*)d_in[1];
    const float* v    = (const float*)d_in[2];
    const float* mask = (const float*)d_in[3];
    const float* ow   = (const float*)d_in[4];
    const float* ob   = (const float*)d_in[5];
    float* out = (float*)d_out;

    cudaFuncSetAttribute(flash_kernel, cudaFuncAttributeMaxDynamicSharedMemorySize,
                         FLASH_SMEM_WORDS * (int)sizeof(uint32_t));

    rope_kernel<<<dim3(SEQ / 32, BH), 256>>>(q, k);
    vT_kernel<<<dim3(SEQ / 64, BH), 256>>>(v);
    qt_mma_kernel<<<dim3(SEQ / 128, BH), 128>>>(mask);
    flash_kernel<<<dim3(SEQ / 128, BH), 256, FLASH_SMEM_WORDS * sizeof(uint32_t)>>>();
    out_mma_kernel<<<dim3(NB * SEQ / 128, DM / 64), 128>>>(ow, ob, out);
}

// round 6
// speedup vs baseline: 2.4106x; 1.1630x over previous
#include <cuda_runtime.h>
#include <math.h>
#include <cstdint>

#define NB   2
#define NH   16
#define BH   (NB*NH)
#define SEQ  2048
#define HD   64
#define DM   1024
#define SCALE 0.125f   // 64^-0.5 (exact power of two)

// ---- scratch (device globals; no allocation APIs allowed) ----
__device__ __align__(16) uint32_t g_qrT_hi[BH*HD*(SEQ/2)];  // rope(q)^T, pairs along seq (qt B-op)
__device__ __align__(16) uint32_t g_qrT_lo[BH*HD*(SEQ/2)];
__device__ __align__(16) uint32_t g_kT_hi [BH*SEQ*(HD/2)];  // rope(k), [key][d-pair] (flash B-op)
__device__ __align__(16) uint32_t g_kT_lo [BH*SEQ*(HD/2)];
__device__ __align__(16) uint32_t g_vt_hi [BH*HD*(SEQ/2)];  // v^T, [d][key-pair] (flash PV B-op)
__device__ __align__(16) uint32_t g_vt_lo [BH*HD*(SEQ/2)];
__device__ __align__(16) uint32_t g_qs_hi [BH*SEQ*(HD/2)];  // scaled qt, [row][d-pair] (flash A-op)
__device__ __align__(16) uint32_t g_qs_lo [BH*SEQ*(HD/2)];
__device__ float g_ctx[NB*SEQ*DM];                          // attention out (b, s, h*d)

// ================= split-bf16 helpers =================
__device__ __forceinline__ void split2(float x, float y, uint32_t& hi, uint32_t& lo) {
    uint32_t h;
    asm("cvt.rn.bf16x2.f32 %0, %1, %2;" : "=r"(h) : "f"(y), "f"(x));  // low<-x, high<-y
    float hx = __uint_as_float(h << 16);
    float hy = __uint_as_float(h & 0xFFFF0000u);
    asm("cvt.rn.bf16x2.f32 %0, %1, %2;" : "=r"(lo) : "f"(y - hy), "f"(x - hx));
    hi = h;
}
__device__ __forceinline__ void split4(float4 a, uint32_t* h2, uint32_t* l2) {
    split2(a.x, a.y, h2[0], l2[0]);
    split2(a.z, a.w, h2[1], l2[1]);
}

__device__ __forceinline__ void mma_bf16(float* c,
        uint32_t a0, uint32_t a1, uint32_t a2, uint32_t a3, uint32_t b0, uint32_t b1) {
    asm volatile("mma.sync.aligned.m16n8k16.row.col.f32.bf16.bf16.f32 "
                 "{%0,%1,%2,%3}, {%4,%5,%6,%7}, {%8,%9}, {%0,%1,%2,%3};"
                 : "+f"(c[0]), "+f"(c[1]), "+f"(c[2]), "+f"(c[3])
                 : "r"(a0), "r"(a1), "r"(a2), "r"(a3), "r"(b0), "r"(b1));
}
// split product: hh + hl + lh  (ll dropped)
__device__ __forceinline__ void mma3(float* c, const uint32_t* ah, const uint32_t* al,
                                     uint32_t bh0, uint32_t bh1, uint32_t bl0, uint32_t bl1) {
    mma_bf16(c, ah[0], ah[1], ah[2], ah[3], bh0, bh1);
    mma_bf16(c, ah[0], ah[1], ah[2], ah[3], bl0, bl1);
    mma_bf16(c, al[0], al[1], al[2], al[3], bh0, bh1);
}

// ================= ldmatrix helpers =================
__device__ __forceinline__ void ldsm_x4(uint32_t* r, uint32_t a) {
    asm volatile("ldmatrix.sync.aligned.m8n8.x4.shared.b16 {%0,%1,%2,%3}, [%4];"
                 : "=r"(r[0]), "=r"(r[1]), "=r"(r[2]), "=r"(r[3]) : "r"(a));
}
__device__ __forceinline__ uint32_t smem_to_u32(const void* p) {
    uint32_t a;
    asm("{ .reg .u64 t; cvta.to.shared.u64 t, %1; cvt.u32.u64 %0, t; }" : "=r"(a) : "l"(p));
    return a;
}
// A-operand: matrices = (rows rb+0..7 | rb+8..15) x (words +0..3 | +4..7)
__device__ __forceinline__ uint32_t addrA(uint32_t base, int rb, int stride, int lane) {
    return base + 4u * ((uint32_t)(rb + (lane & 15)) * stride + ((lane >> 4) & 1) * 4);
}
// B-operand: matrices = (b0 | b1) for nt, then nt+1: rows (lane&7)+8*(lane>>4), words 4*((lane>>3)&1)
__device__ __forceinline__ uint32_t addrB(uint32_t base, int stride, int lane) {
    return base + 4u * ((uint32_t)((lane & 7) + ((lane >> 4) & 1) * 8) * stride
                       + ((lane >> 3) & 1) * 4);
}

// ============================================================
// 1) RoPE: q -> g_qrT (pairs along seq, for qt B-op); k -> g_kT (pairs along d, for flash)
// ============================================================
__global__ __launch_bounds__(256) void rope_kernel(const float* __restrict__ q,
                                                   const float* __restrict__ k) {
    __shared__ float qs[64][33];    // [d][s_local]
    __shared__ float ks2[32][66];   // [s_local][d]
    int t = threadIdx.x;
    int bh = blockIdx.y;
    int s0 = blockIdx.x * 32;
    int d  = t & 31;
    float inv_freq = 1.0f / powf(10000.0f, (float)(2 * d) * (1.0f / 64.0f));
#pragma unroll
    for (int j = 0; j < 4; j++) {
        int sl = j * 8 + (t >> 5);
        int s = s0 + sl;
        float sn, cs;
        sincosf((float)s * inv_freq, &sn, &cs);
        size_t base = ((size_t)bh * SEQ + s) * HD;
        float a1 = q[base + d], a2 = q[base + d + 32];
        qs[d][sl]      = a1 * cs - a2 * sn;
        qs[d + 32][sl] = a2 * cs + a1 * sn;
        float b1 = k[base + d], b2 = k[base + d + 32];
        ks2[sl][d]      = b1 * cs - b2 * sn;
        ks2[sl][d + 32] = b2 * cs + b1 * sn;
    }
    __syncthreads();
#pragma unroll
    for (int j = 0; j < 4; j++) {     // q out: [d][seq-pair]
        int idx = j * 256 + t;
        int dd = idx >> 4, sp = idx & 15;
        uint32_t hi, lo;
        split2(qs[dd][2 * sp], qs[dd][2 * sp + 1], hi, lo);
        size_t o = ((size_t)bh * HD + dd) * (SEQ / 2) + s0 / 2 + sp;
        g_qrT_hi[o] = hi; g_qrT_lo[o] = lo;
    }
#pragma unroll
    for (int j = 0; j < 4; j++) {     // k out: [key][d-pair]
        int idx = j * 256 + t;
        int sl = idx >> 5, w = idx & 31;
        uint32_t hi, lo;
        split2(ks2[sl][2 * w], ks2[sl][2 * w + 1], hi, lo);
        size_t o = ((size_t)bh * SEQ + s0 + sl) * 32 + w;
        g_kT_hi[o] = hi; g_kT_lo[o] = lo;
    }
}

// ============================================================
// 1b) V transpose: g_vt[d][seq-pairs] bf16 hi/lo
// ============================================================
__global__ __launch_bounds__(256) void vT_kernel(const float* __restrict__ v) {
    __shared__ float vs[64][65];
    int t = threadIdx.x;
    int bh = blockIdx.y;
    int s0 = blockIdx.x * 64;
#pragma unroll
    for (int j = 0; j < 16; j++) {
        int idx = j * 256 + t;
        int sl = idx >> 6, d = idx & 63;
        vs[sl][d] = v[((size_t)bh * SEQ + s0 + sl) * HD + d];
    }
    __syncthreads();
#pragma unroll
    for (int j = 0; j < 8; j++) {
        int idx = j * 256 + t;
        int d = idx >> 5, sp = idx & 31;
        uint32_t hi, lo;
        split2(vs[2 * sp][d], vs[2 * sp + 1][d], hi, lo);
        size_t o = ((size_t)bh * HD + d) * (SEQ / 2) + s0 / 2 + sp;
        g_vt_hi[o] = hi; g_vt_lo[o] = lo;
    }
}

// ============================================================
// 2) qt = W[h] @ qr   (split-bf16 warp-MMA + ldmatrix)
//    Epilogue writes SCALED split Q in flash A-fragment layout.
// ============================================================
#define GSTR 20
__global__ __launch_bounds__(128) void qt_mma_kernel(const float* __restrict__ mask) {
    __shared__ uint32_t Ah[128 * GSTR], Al[128 * GSTR];
    __shared__ uint32_t Bh[64 * GSTR],  Bl[64 * GSTR];
    int t = threadIdx.x, w = t >> 5, lane = t & 31;
    int g = lane >> 2, tig = lane & 3;
    int bh = blockIdx.y, h = bh & (NH - 1);
    int row0 = blockIdx.x * 128;
    const float* Ap = mask + (size_t)h * SEQ * SEQ + (size_t)row0 * SEQ;
    const uint32_t* Bph = g_qrT_hi + (size_t)bh * HD * (SEQ / 2);
    const uint32_t* Bpl = g_qrT_lo + (size_t)bh * HD * (SEQ / 2);

    uint32_t aAh = addrA(smem_to_u32(Ah), w * 32, GSTR, lane);
    uint32_t aAl = addrA(smem_to_u32(Al), w * 32, GSTR, lane);
    uint32_t aBh = addrB(smem_to_u32(Bh), GSTR, lane);
    uint32_t aBl = addrB(smem_to_u32(Bl), GSTR, lane);

    float acc[2][8][4];
#pragma unroll
    for (int mt = 0; mt < 2; mt++)
#pragma unroll
        for (int nt = 0; nt < 8; nt++)
#pragma unroll
            for (int e = 0; e < 4; e++) acc[mt][nt][e] = 0.f;

    for (int c = 0; c < SEQ / 32; c++) {
        int k0 = c * 32;
#pragma unroll
        for (int j = 0; j < 8; j++) {      // A: fp32 -> split
            int idx = j * 128 + t;
            int row = idx >> 3, kg = idx & 7;
            float4 a = *(const float4*)(Ap + (size_t)row * SEQ + k0 + kg * 4);
            uint32_t h2[2], l2[2]; split4(a, h2, l2);
            Ah[row * GSTR + kg * 2] = h2[0]; Ah[row * GSTR + kg * 2 + 1] = h2[1];
            Al[row * GSTR + kg * 2] = l2[0]; Al[row * GSTR + kg * 2 + 1] = l2[1];
        }
#pragma unroll
        for (int j = 0; j < 2; j++) {      // B: pre-split word copy (uint4)
            int u = j * 128 + t;
            int row = u >> 2, wq = (u & 3) * 4;
            *(uint4*)&Bh[row * GSTR + wq] = *(const uint4*)&Bph[(size_t)row * (SEQ / 2) + k0 / 2 + wq];
            *(uint4*)&Bl[row * GSTR + wq] = *(const uint4*)&Bpl[(size_t)row * (SEQ / 2) + k0 / 2 + wq];
        }
        __syncthreads();
#pragma unroll
        for (int ks = 0; ks < 2; ks++) {
            uint32_t ah[2][4], al[2][4];
            ldsm_x4(ah[0], aAh + ks * 32);
            ldsm_x4(ah[1], aAh + 16 * GSTR * 4 + ks * 32);
            ldsm_x4(al[0], aAl + ks * 32);
            ldsm_x4(al[1], aAl + 16 * GSTR * 4 + ks * 32);
#pragma unroll
            for (int np = 0; np < 4; np++) {
                uint32_t kh4[4], kl4[4];
                ldsm_x4(kh4, aBh + np * (16 * GSTR * 4) + ks * 32);
                ldsm_x4(kl4, aBl + np * (16 * GSTR * 4) + ks * 32);
                mma3(acc[0][2*np],   ah[0], al[0], kh4[0], kh4[1], kl4[0], kl4[1]);
                mma3(acc[0][2*np+1], ah[0], al[0], kh4[2], kh4[3], kl4[2], kl4[3]);
                mma3(acc[1][2*np],   ah[1], al[1], kh4[0], kh4[1], kl4[0], kl4[1]);
                mma3(acc[1][2*np+1], ah[1], al[1], kh4[2], kh4[3], kl4[2], kl4[3]);
            }
        }
        __syncthreads();
    }
    // epilogue: scale (exact pow2), split, store in [row][d-pair] layout
    size_t ro = (size_t)bh * SEQ + row0;
#pragma unroll
    for (int mt = 0; mt < 2; mt++)
#pragma unroll
        for (int nt = 0; nt < 8; nt++) {
            uint32_t hi, lo;
            size_t r0 = ro + w * 32 + mt * 16 + g;
            split2(acc[mt][nt][0] * SCALE, acc[mt][nt][1] * SCALE, hi, lo);
            g_qs_hi[r0 * 32 + nt * 4 + tig] = hi;
            g_qs_lo[r0 * 32 + nt * 4 + tig] = lo;
            split2(acc[mt][nt][2] * SCALE, acc[mt][nt][3] * SCALE, hi, lo);
            g_qs_hi[(r0 + 8) * 32 + nt * 4 + tig] = hi;
            g_qs_lo[(r0 + 8) * 32 + nt * 4 + tig] = lo;
        }
}

// ============================================================
// 3) Flash attention: split-bf16 FA2, all staging = word copies, ldmatrix fragments
// ============================================================
#define FSTR 36
#define FQ_H 0
#define FQ_L (FQ_H + 128*FSTR)
#define FK_H (FQ_L + 128*FSTR)
#define FK_L (FK_H + 64*FSTR)
#define FV_H (FK_L + 64*FSTR)
#define FV_L (FV_H + 64*FSTR)
#define FLASH_SMEM_WORDS (FV_L + 64*FSTR)   // 18432 words = 73728 B

__global__ __launch_bounds__(256, 2) void flash_kernel() {
    extern __shared__ uint32_t fsm[];
    uint32_t* Qh = fsm + FQ_H; uint32_t* Ql = fsm + FQ_L;
    uint32_t* Kh = fsm + FK_H; uint32_t* Kl = fsm + FK_L;
    uint32_t* Vh = fsm + FV_H; uint32_t* Vl = fsm + FV_L;

    int t = threadIdx.x, w = t >> 5, lane = t & 31;
    int bh = blockIdx.y;
    int b = bh >> 4, h = bh & 15;
    int q0 = blockIdx.x * 128;
    int rb = w * 16;

    uint32_t sb = smem_to_u32(fsm);
    uint32_t aQh = addrA(sb + 4 * FQ_H, rb, FSTR, lane);
    uint32_t aQl = addrA(sb + 4 * FQ_L, rb, FSTR, lane);
    uint32_t aKh = addrB(sb + 4 * FK_H, FSTR, lane);
    uint32_t aKl = addrB(sb + 4 * FK_L, FSTR, lane);
    uint32_t aVh = addrB(sb + 4 * FV_H, FSTR, lane);
    uint32_t aVl = addrB(sb + 4 * FV_L, FSTR, lane);

    const uint32_t* qph = g_qs_hi + ((size_t)bh * SEQ + q0) * 32;
    const uint32_t* qpl = g_qs_lo + ((size_t)bh * SEQ + q0) * 32;
    const uint32_t* kph = g_kT_hi + (size_t)bh * SEQ * 32;
    const uint32_t* kpl = g_kT_lo + (size_t)bh * SEQ * 32;
    const uint32_t* vph = g_vt_hi + (size_t)bh * HD * (SEQ / 2);
    const uint32_t* vpl = g_vt_lo + (size_t)bh * HD * (SEQ / 2);

    // stage Q once (pure copy)
#pragma unroll
    for (int j = 0; j < 4; j++) {
        int u = j * 256 + t;
        int row = u >> 3, wq = (u & 7) * 4;
        *(uint4*)&Qh[row * FSTR + wq] = *(const uint4*)&qph[row * 32 + wq];
        *(uint4*)&Ql[row * FSTR + wq] = *(const uint4*)&qpl[row * 32 + wq];
    }

    float m0 = -1e30f, m1 = -1e30f, l0 = 0.f, l1 = 0.f;
    float ctx[8][4];
#pragma unroll
    for (int nt = 0; nt < 8; nt++)
#pragma unroll
        for (int e = 0; e < 4; e++) ctx[nt][e] = 0.f;

    for (int kt = 0; kt < SEQ / 64; kt++) {
        __syncthreads();
        // stage K + V tiles (pure copies)
#pragma unroll
        for (int j = 0; j < 2; j++) {
            int u = j * 256 + t;
            int row = u >> 3, wq = (u & 7) * 4;
            *(uint4*)&Kh[row * FSTR + wq] = *(const uint4*)&kph[(size_t)(kt * 64 + row) * 32 + wq];
            *(uint4*)&Kl[row * FSTR + wq] = *(const uint4*)&kpl[(size_t)(kt * 64 + row) * 32 + wq];
            *(uint4*)&Vh[row * FSTR + wq] = *(const uint4*)&vph[(size_t)row * (SEQ / 2) + kt * 32 + wq];
            *(uint4*)&Vl[row * FSTR + wq] = *(const uint4*)&vpl[(size_t)row * (SEQ / 2) + kt * 32 + wq];
        }
        __syncthreads();

        // S = Q @ K^T (16x64 per warp)
        float s[8][4];
#pragma unroll
        for (int nt = 0; nt < 8; nt++)
#pragma unroll
            for (int e = 0; e < 4; e++) s[nt][e] = 0.f;
#pragma unroll
        for (int ks = 0; ks < 4; ks++) {
            uint32_t qh4[4], ql4[4];
            ldsm_x4(qh4, aQh + ks * 32);
            ldsm_x4(ql4, aQl + ks * 32);
#pragma unroll
            for (int np = 0; np < 4; np++) {
                uint32_t kh4[4], kl4[4];
                ldsm_x4(kh4, aKh + np * (16 * FSTR * 4) + ks * 32);
                ldsm_x4(kl4, aKl + np * (16 * FSTR * 4) + ks * 32);
                mma3(s[2*np],   qh4, ql4, kh4[0], kh4[1], kl4[0], kl4[1]);
                mma3(s[2*np+1], qh4, ql4, kh4[2], kh4[3], kl4[2], kl4[3]);
            }
        }

        // online softmax
        float rm0 = -1e30f, rm1 = -1e30f;
#pragma unroll
        for (int nt = 0; nt < 8; nt++) {
            rm0 = fmaxf(rm0, fmaxf(s[nt][0], s[nt][1]));
            rm1 = fmaxf(rm1, fmaxf(s[nt][2], s[nt][3]));
        }
        rm0 = fmaxf(rm0, __shfl_xor_sync(0xffffffffu, rm0, 1));
        rm0 = fmaxf(rm0, __shfl_xor_sync(0xffffffffu, rm0, 2));
        rm1 = fmaxf(rm1, __shfl_xor_sync(0xffffffffu, rm1, 1));
        rm1 = fmaxf(rm1, __shfl_xor_sync(0xffffffffu, rm1, 2));
        float mn0 = fmaxf(m0, rm0), mn1 = fmaxf(m1, rm1);
        float corr0 = __expf(m0 - mn0), corr1 = __expf(m1 - mn1);
        m0 = mn0; m1 = mn1;
        float rs0 = 0.f, rs1 = 0.f;
#pragma unroll
        for (int nt = 0; nt < 8; nt++) {
            s[nt][0] = __expf(s[nt][0] - mn0); rs0 += s[nt][0];
            s[nt][1] = __expf(s[nt][1] - mn0); rs0 += s[nt][1];
            s[nt][2] = __expf(s[nt][2] - mn1); rs1 += s[nt][2];
            s[nt][3] = __expf(s[nt][3] - mn1); rs1 += s[nt][3];
        }
        rs0 += __shfl_xor_sync(0xffffffffu, rs0, 1);
        rs0 += __shfl_xor_sync(0xffffffffu, rs0, 2);
        rs1 += __shfl_xor_sync(0xffffffffu, rs1, 1);
        rs1 += __shfl_xor_sync(0xffffffffu, rs1, 2);
        l0 = l0 * corr0 + rs0;
        l1 = l1 * corr1 + rs1;
#pragma unroll
        for (int nt = 0; nt < 8; nt++) {
            ctx[nt][0] *= corr0; ctx[nt][1] *= corr0;
            ctx[nt][2] *= corr1; ctx[nt][3] *= corr1;
        }

        // ctx += P @ V  (P fragments from registers)
#pragma unroll
        for (int ks = 0; ks < 4; ks++) {
            uint32_t ph[4], pl[4];
            split2(s[2*ks][0],   s[2*ks][1],   ph[0], pl[0]);
            split2(s[2*ks][2],   s[2*ks][3],   ph[1], pl[1]);
            split2(s[2*ks+1][0], s[2*ks+1][1], ph[2], pl[2]);
            split2(s[2*ks+1][2], s[2*ks+1][3], ph[3], pl[3]);
#pragma unroll
            for (int np = 0; np < 4; np++) {
                uint32_t vh4[4], vl4[4];
                ldsm_x4(vh4, aVh + np * (16 * FSTR * 4) + ks * 32);
                ldsm_x4(vl4, aVl + np * (16 * FSTR * 4) + ks * 32);
                mma3(ctx[2*np],   ph, pl, vh4[0], vh4[1], vl4[0], vl4[1]);
                mma3(ctx[2*np+1], ph, pl, vh4[2], vh4[3], vl4[2], vl4[3]);
            }
        }
    }

    int g = lane >> 2, tig = lane & 3;
    float invl0 = 1.0f / l0, invl1 = 1.0f / l1;
    int r0 = q0 + rb + g;
#pragma unroll
    for (int nt = 0; nt < 8; nt++) {
        int col = h * HD + nt * 8 + 2 * tig;
        *(float2*)(g_ctx + ((size_t)b * SEQ + r0) * DM + col) =
            make_float2(ctx[nt][0] * invl0, ctx[nt][1] * invl0);
        *(float2*)(g_ctx + ((size_t)b * SEQ + r0 + 8) * DM + col) =
            make_float2(ctx[nt][2] * invl1, ctx[nt][3] * invl1);
    }
}

// ============================================================
// 4) out = ctx @ out_w^T + out_b  (split-bf16 warp-MMA + ldmatrix)
// ============================================================
__global__ __launch_bounds__(128) void out_mma_kernel(const float* __restrict__ wgt,
                                                      const float* __restrict__ bias,
                                                      float* __restrict__ out) {
    __shared__ uint32_t Ah[128 * GSTR], Al[128 * GSTR];
    __shared__ uint32_t Bh[64 * GSTR],  Bl[64 * GSTR];
    int t = threadIdx.x, w = t >> 5, lane = t & 31;
    int g = lane >> 2, tig = lane & 3;
    int row0 = blockIdx.x * 128;
    int col0 = blockIdx.y * 64;
    const float* Ap = g_ctx + (size_t)row0 * DM;
    const float* Bp = wgt   + (size_t)col0 * DM;

    uint32_t aAh = addrA(smem_to_u32(Ah), w * 32, GSTR, lane);
    uint32_t aAl = addrA(smem_to_u32(Al), w * 32, GSTR, lane);
    uint32_t aBh = addrB(smem_to_u32(Bh), GSTR, lane);
    uint32_t aBl = addrB(smem_to_u32(Bl), GSTR, lane);

    float acc[2][8][4];
#pragma unroll
    for (int mt = 0; mt < 2; mt++)
#pragma unroll
        for (int nt = 0; nt < 8; nt++)
#pragma unroll
            for (int e = 0; e < 4; e++) acc[mt][nt][e] = 0.f;

    for (int c = 0; c < DM / 32; c++) {
        int k0 = c * 32;
#pragma unroll
        for (int j = 0; j < 8; j++) {
            int idx = j * 128 + t;
            int row = idx >> 3, kg = idx & 7;
            float4 a = *(const float4*)(Ap + (size_t)row * DM + k0 + kg * 4);
            uint32_t h2[2], l2[2]; split4(a, h2, l2);
            Ah[row * GSTR + kg * 2] = h2[0]; Ah[row * GSTR + kg * 2 + 1] = h2[1];
            Al[row * GSTR + kg * 2] = l2[0]; Al[row * GSTR + kg * 2 + 1] = l2[1];
        }
#pragma unroll
        for (int j = 0; j < 4; j++) {
            int idx = j * 128 + t;
            int n = idx >> 3, kg = idx & 7;
            float4 a = *(const float4*)(Bp + (size_t)n * DM + k0 + kg * 4);
            uint32_t h2[2], l2[2]; split4(a, h2, l2);
            Bh[n * GSTR + kg * 2] = h2[0]; Bh[n * GSTR + kg * 2 + 1] = h2[1];
            Bl[n * GSTR + kg * 2] = l2[0]; Bl[n * GSTR + kg * 2 + 1] = l2[1];
        }
        __syncthreads();
#pragma unroll
        for (int ks = 0; ks < 2; ks++) {
            uint32_t ah[2][4], al[2][4];
            ldsm_x4(ah[0], aAh + ks * 32);
            ldsm_x4(ah[1], aAh + 16 * GSTR * 4 + ks * 32);
            ldsm_x4(al[0], aAl + ks * 32);
            ldsm_x4(al[1], aAl + 16 * GSTR * 4 + ks * 32);
#pragma unroll
            for (int np = 0; np < 4; np++) {
                uint32_t kh4[4], kl4[4];
                ldsm_x4(kh4, aBh + np * (16 * GSTR * 4) + ks * 32);
                ldsm_x4(kl4, aBl + np * (16 * GSTR * 4) + ks * 32);
                mma3(acc[0][2*np],   ah[0], al[0], kh4[0], kh4[1], kl4[0], kl4[1]);
                mma3(acc[0][2*np+1], ah[0], al[0], kh4[2], kh4[3], kl4[2], kl4[3]);
                mma3(acc[1][2*np],   ah[1], al[1], kh4[0], kh4[1], kl4[0], kl4[1]);
                mma3(acc[1][2*np+1], ah[1], al[1], kh4[2], kh4[3], kl4[2], kl4[3]);
            }
        }
        __syncthreads();
    }
#pragma unroll
    for (int mt = 0; mt < 2; mt++)
#pragma unroll
        for (int nt = 0; nt < 8; nt++) {
            int col = col0 + nt * 8 + 2 * tig;
            size_t r0 = row0 + w * 32 + mt * 16 + g;
            float2 bi = *(const float2*)(bias + col);
            *(float2*)(out + r0 * DM + col) =
                make_float2(acc[mt][nt][0] + bi.x, acc[mt][nt][1] + bi.y);
            *(float2*)(out + (r0 + 8) * DM + col) =
                make_float2(acc[mt][nt][2] + bi.x, acc[mt][nt][3] + bi.y);
        }
}

// ============================================================
extern "C" void kernel_launch(void* const* d_in, const int* in_sizes, int n_in,
                              void* d_out, int out_size) {
    (void)in_sizes; (void)n_in; (void)out_size;
    const float* q    = (const float*)d_in[0];
    const float* k    = (const float*)d_in[1];
    const float* v    = (const float*)d_in[2];
    const float* mask = (const float*)d_in[3];
    const float* ow   = (const float*)d_in[4];
    const float* ob   = (const float*)d_in[5];
    float* out = (float*)d_out;

    cudaFuncSetAttribute(flash_kernel, cudaFuncAttributeMaxDynamicSharedMemorySize,
                         FLASH_SMEM_WORDS * (int)sizeof(uint32_t));

    rope_kernel<<<dim3(SEQ / 32, BH), 256>>>(q, k);
    vT_kernel<<<dim3(SEQ / 64, BH), 256>>>(v);
    qt_mma_kernel<<<dim3(SEQ / 128, BH), 128>>>(mask);
    flash_kernel<<<dim3(SEQ / 128, BH), 256, FLASH_SMEM_WORDS * sizeof(uint32_t)>>>();
    out_mma_kernel<<<dim3(NB * SEQ / 128, DM / 64), 128>>>(ow, ob, out);
}

// round 7
// speedup vs baseline: 2.8530x; 1.1835x over previous
#include <cuda_runtime.h>
#include <math.h>
#include <cstdint>

#define NB   2
#define NH   16
#define BH   (NB*NH)
#define SEQ  2048
#define HD   64
#define DM   1024
#define SCALE 0.125f
#define LOG2E 1.4426950408889634f

// ---- scratch (device globals; no allocation APIs allowed) ----
__device__ __align__(16) uint32_t g_qrT_hi[BH*HD*(SEQ/2)];  // rope(q)^T pairs-along-seq (qt B-op)
__device__ __align__(16) uint32_t g_qrT_lo[BH*HD*(SEQ/2)];
__device__ __align__(16) uint32_t g_kT_hi [BH*SEQ*(HD/2)];  // rope(k) [key][d-pair] (flash B-op)
__device__ __align__(16) uint32_t g_kT_lo [BH*SEQ*(HD/2)];
__device__ __align__(16) uint32_t g_vt_hi [BH*HD*(SEQ/2)];  // v^T [d][key-pair] (flash PV B-op)
__device__ __align__(16) uint32_t g_vt_lo [BH*HD*(SEQ/2)];
__device__ __align__(16) uint32_t g_qs_hi [BH*SEQ*(HD/2)];  // scaled qt [row][d-pair] (flash A-op)
__device__ __align__(16) uint32_t g_qs_lo [BH*SEQ*(HD/2)];
__device__ float g_ctx[NB*SEQ*DM];

// ================= split-bf16 helpers =================
__device__ __forceinline__ void split2(float x, float y, uint32_t& hi, uint32_t& lo) {
    uint32_t h;
    asm("cvt.rn.bf16x2.f32 %0, %1, %2;" : "=r"(h) : "f"(y), "f"(x));
    float hx = __uint_as_float(h << 16);
    float hy = __uint_as_float(h & 0xFFFF0000u);
    asm("cvt.rn.bf16x2.f32 %0, %1, %2;" : "=r"(lo) : "f"(y - hy), "f"(x - hx));
    hi = h;
}
__device__ __forceinline__ void split4(float4 a, uint32_t* h2, uint32_t* l2) {
    split2(a.x, a.y, h2[0], l2[0]);
    split2(a.z, a.w, h2[1], l2[1]);
}
__device__ __forceinline__ void mma_bf16(float* c,
        uint32_t a0, uint32_t a1, uint32_t a2, uint32_t a3, uint32_t b0, uint32_t b1) {
    asm volatile("mma.sync.aligned.m16n8k16.row.col.f32.bf16.bf16.f32 "
                 "{%0,%1,%2,%3}, {%4,%5,%6,%7}, {%8,%9}, {%0,%1,%2,%3};"
                 : "+f"(c[0]), "+f"(c[1]), "+f"(c[2]), "+f"(c[3])
                 : "r"(a0), "r"(a1), "r"(a2), "r"(a3), "r"(b0), "r"(b1));
}
__device__ __forceinline__ void mma3(float* c, const uint32_t* ah, const uint32_t* al,
                                     uint32_t bh0, uint32_t bh1, uint32_t bl0, uint32_t bl1) {
    mma_bf16(c, ah[0], ah[1], ah[2], ah[3], bh0, bh1);
    mma_bf16(c, ah[0], ah[1], ah[2], ah[3], bl0, bl1);
    mma_bf16(c, al[0], al[1], al[2], al[3], bh0, bh1);
}

// ================= ldmatrix / cp.async / misc =================
__device__ __forceinline__ void ldsm_x4(uint32_t* r, uint32_t a) {
    asm volatile("ldmatrix.sync.aligned.m8n8.x4.shared.b16 {%0,%1,%2,%3}, [%4];"
                 : "=r"(r[0]), "=r"(r[1]), "=r"(r[2]), "=r"(r[3]) : "r"(a));
}
__device__ __forceinline__ uint32_t smem_to_u32(const void* p) {
    uint32_t a;
    asm("{ .reg .u64 t; cvta.to.shared.u64 t, %1; cvt.u32.u64 %0, t; }" : "=r"(a) : "l"(p));
    return a;
}
__device__ __forceinline__ void cp16(uint32_t saddr, const void* g) {
    asm volatile("cp.async.cg.shared.global [%0], [%1], 16;" :: "r"(saddr), "l"(g));
}
#define CP_COMMIT() asm volatile("cp.async.commit_group;" ::: "memory")
#define CP_WAIT0()  asm volatile("cp.async.wait_group 0;" ::: "memory")
__device__ __forceinline__ float ex2f(float x) {
    float y; asm("ex2.approx.f32 %0, %1;" : "=f"(y) : "f"(x)); return y;
}
// lane-offset (bytes) for A-operand ldmatrix x4 (16 rows x 16 cols region)
__device__ __forceinline__ uint32_t offA(int rb, int stride, int lane) {
    return 4u * ((uint32_t)(rb + (lane & 15)) * stride + ((lane >> 4) & 1) * 4);
}
// lane-offset (bytes) for B-operand ldmatrix x4
__device__ __forceinline__ uint32_t offB(int stride, int lane) {
    return 4u * ((uint32_t)((lane & 7) + ((lane >> 4) & 1) * 8) * stride
                 + ((lane >> 3) & 1) * 4);
}

// ============================================================
// 1) RoPE
// ============================================================
__global__ __launch_bounds__(256) void rope_kernel(const float* __restrict__ q,
                                                   const float* __restrict__ k) {
    __shared__ float qs[64][33];
    __shared__ float ks2[32][66];
    int t = threadIdx.x;
    int bh = blockIdx.y;
    int s0 = blockIdx.x * 32;
    int d  = t & 31;
    float inv_freq = 1.0f / powf(10000.0f, (float)(2 * d) * (1.0f / 64.0f));
#pragma unroll
    for (int j = 0; j < 4; j++) {
        int sl = j * 8 + (t >> 5);
        int s = s0 + sl;
        float sn, cs;
        sincosf((float)s * inv_freq, &sn, &cs);
        size_t base = ((size_t)bh * SEQ + s) * HD;
        float a1 = q[base + d], a2 = q[base + d + 32];
        qs[d][sl]      = a1 * cs - a2 * sn;
        qs[d + 32][sl] = a2 * cs + a1 * sn;
        float b1 = k[base + d], b2 = k[base + d + 32];
        ks2[sl][d]      = b1 * cs - b2 * sn;
        ks2[sl][d + 32] = b2 * cs + b1 * sn;
    }
    __syncthreads();
#pragma unroll
    for (int j = 0; j < 4; j++) {
        int idx = j * 256 + t;
        int dd = idx >> 4, sp = idx & 15;
        uint32_t hi, lo;
        split2(qs[dd][2 * sp], qs[dd][2 * sp + 1], hi, lo);
        size_t o = ((size_t)bh * HD + dd) * (SEQ / 2) + s0 / 2 + sp;
        g_qrT_hi[o] = hi; g_qrT_lo[o] = lo;
    }
#pragma unroll
    for (int j = 0; j < 4; j++) {
        int idx = j * 256 + t;
        int sl = idx >> 5, w = idx & 31;
        uint32_t hi, lo;
        split2(ks2[sl][2 * w], ks2[sl][2 * w + 1], hi, lo);
        size_t o = ((size_t)bh * SEQ + s0 + sl) * 32 + w;
        g_kT_hi[o] = hi; g_kT_lo[o] = lo;
    }
}

// ============================================================
// 1b) V transpose
// ============================================================
__global__ __launch_bounds__(256) void vT_kernel(const float* __restrict__ v) {
    __shared__ float vs[64][65];
    int t = threadIdx.x;
    int bh = blockIdx.y;
    int s0 = blockIdx.x * 64;
#pragma unroll
    for (int j = 0; j < 16; j++) {
        int idx = j * 256 + t;
        int sl = idx >> 6, d = idx & 63;
        vs[sl][d] = v[((size_t)bh * SEQ + s0 + sl) * HD + d];
    }
    __syncthreads();
#pragma unroll
    for (int j = 0; j < 8; j++) {
        int idx = j * 256 + t;
        int d = idx >> 5, sp = idx & 31;
        uint32_t hi, lo;
        split2(vs[2 * sp][d], vs[2 * sp + 1][d], hi, lo);
        size_t o = ((size_t)bh * HD + d) * (SEQ / 2) + s0 / 2 + sp;
        g_vt_hi[o] = hi; g_vt_lo[o] = lo;
    }
}

// ============================================================
// 2) qt = W[h] @ qr -- register-prefetch double-buffered, 1 barrier/iter
//    Epilogue stores qt * (SCALE*LOG2E), split, in flash A layout.
// ============================================================
#define GSTR 20
#define QA_H 0
#define QA_L 2560
#define QB_H 5120
#define QB_L 6400
#define QBUF 7680                       // words per buffer
#define QT_SMEM_BYTES (2*QBUF*4)        // 61440

__global__ __launch_bounds__(128) void qt_mma_kernel(const float* __restrict__ mask) {
    extern __shared__ uint32_t qsm[];
    int t = threadIdx.x, w = t >> 5, lane = t & 31;
    int g = lane >> 2, tig = lane & 3;
    int yb = blockIdx.y;
    int h = yb >> 1, b = yb & 1;        // h-major pairing: same-W CTAs adjacent (L2 reuse)
    int bh = b * NH + h;
    int row0 = blockIdx.x * 128;
    const float* Ap = mask + (size_t)h * SEQ * SEQ + (size_t)row0 * SEQ;
    const uint32_t* Bph = g_qrT_hi + (size_t)bh * HD * (SEQ / 2);
    const uint32_t* Bpl = g_qrT_lo + (size_t)bh * HD * (SEQ / 2);

    uint32_t sb = smem_to_u32(qsm);
    uint32_t oA = offA(w * 32, GSTR, lane);
    uint32_t oBf = offB(GSTR, lane);

    float acc[2][8][4];
#pragma unroll
    for (int mt = 0; mt < 2; mt++)
#pragma unroll
        for (int nt = 0; nt < 8; nt++)
#pragma unroll
            for (int e = 0; e < 4; e++) acc[mt][nt][e] = 0.f;

    float4 aR[8]; uint4 bhR[2], blR[2];
    // preload chunk 0
#pragma unroll
    for (int j = 0; j < 8; j++) {
        int idx = j * 128 + t;
        int row = idx >> 3, kg = idx & 7;
        aR[j] = *(const float4*)(Ap + (size_t)row * SEQ + kg * 4);
    }
#pragma unroll
    for (int j = 0; j < 2; j++) {
        int u = j * 128 + t;
        int row = u >> 2, wq = (u & 3) * 4;
        bhR[j] = *(const uint4*)&Bph[(size_t)row * (SEQ / 2) + wq];
        blR[j] = *(const uint4*)&Bpl[(size_t)row * (SEQ / 2) + wq];
    }

    const int NC = SEQ / 32;
    for (int c = 0; c < NC; c++) {
        int cur = c & 1;
        uint32_t* Ah = qsm + cur * QBUF + QA_H;
        uint32_t* Al = qsm + cur * QBUF + QA_L;
        uint32_t* Bh = qsm + cur * QBUF + QB_H;
        uint32_t* Bl = qsm + cur * QBUF + QB_L;
#pragma unroll
        for (int j = 0; j < 8; j++) {
            int idx = j * 128 + t;
            int row = idx >> 3, kg = idx & 7;
            uint32_t h2[2], l2[2]; split4(aR[j], h2, l2);
            Ah[row * GSTR + kg * 2] = h2[0]; Ah[row * GSTR + kg * 2 + 1] = h2[1];
            Al[row * GSTR + kg * 2] = l2[0]; Al[row * GSTR + kg * 2 + 1] = l2[1];
        }
#pragma unroll
        for (int j = 0; j < 2; j++) {
            int u = j * 128 + t;
            int row = u >> 2, wq = (u & 3) * 4;
            *(uint4*)&Bh[row * GSTR + wq] = bhR[j];
            *(uint4*)&Bl[row * GSTR + wq] = blR[j];
        }
        __syncthreads();
        if (c + 1 < NC) {       // prefetch next chunk into registers (overlaps MMAs)
            int k0 = (c + 1) * 32;
#pragma unroll
            for (int j = 0; j < 8; j++) {
                int idx = j * 128 + t;
                int row = idx >> 3, kg = idx & 7;
                aR[j] = *(const float4*)(Ap + (size_t)row * SEQ + k0 + kg * 4);
            }
#pragma unroll
            for (int j = 0; j < 2; j++) {
                int u = j * 128 + t;
                int row = u >> 2, wq = (u & 3) * 4;
                bhR[j] = *(const uint4*)&Bph[(size_t)row * (SEQ / 2) + k0 / 2 + wq];
                blR[j] = *(const uint4*)&Bpl[(size_t)row * (SEQ / 2) + k0 / 2 + wq];
            }
        }
        uint32_t aAh = sb + 4u * (cur * QBUF + QA_H) + oA;
        uint32_t aAl = sb + 4u * (cur * QBUF + QA_L) + oA;
        uint32_t aBh = sb + 4u * (cur * QBUF + QB_H) + oBf;
        uint32_t aBl = sb + 4u * (cur * QBUF + QB_L) + oBf;
#pragma unroll
        for (int ks = 0; ks < 2; ks++) {
            uint32_t ah[2][4], al[2][4];
            ldsm_x4(ah[0], aAh + ks * 32);
            ldsm_x4(ah[1], aAh + 16 * GSTR * 4 + ks * 32);
            ldsm_x4(al[0], aAl + ks * 32);
            ldsm_x4(al[1], aAl + 16 * GSTR * 4 + ks * 32);
#pragma unroll
            for (int np = 0; np < 4; np++) {
                uint32_t kh4[4], kl4[4];
                ldsm_x4(kh4, aBh + np * (16 * GSTR * 4) + ks * 32);
                ldsm_x4(kl4, aBl + np * (16 * GSTR * 4) + ks * 32);
                mma3(acc[0][2*np],   ah[0], al[0], kh4[0], kh4[1], kl4[0], kl4[1]);
                mma3(acc[0][2*np+1], ah[0], al[0], kh4[2], kh4[3], kl4[2], kl4[3]);
                mma3(acc[1][2*np],   ah[1], al[1], kh4[0], kh4[1], kl4[0], kl4[1]);
                mma3(acc[1][2*np+1], ah[1], al[1], kh4[2], kh4[3], kl4[2], kl4[3]);
            }
        }
    }
    const float SC = SCALE * LOG2E;   // exp2-domain scores
    size_t ro = (size_t)bh * SEQ + row0;
#pragma unroll
    for (int mt = 0; mt < 2; mt++)
#pragma unroll
        for (int nt = 0; nt < 8; nt++) {
            uint32_t hi, lo;
            size_t r0 = ro + w * 32 + mt * 16 + g;
            split2(acc[mt][nt][0] * SC, acc[mt][nt][1] * SC, hi, lo);
            g_qs_hi[r0 * 32 + nt * 4 + tig] = hi;
            g_qs_lo[r0 * 32 + nt * 4 + tig] = lo;
            split2(acc[mt][nt][2] * SC, acc[mt][nt][3] * SC, hi, lo);
            g_qs_hi[(r0 + 8) * 32 + nt * 4 + tig] = hi;
            g_qs_lo[(r0 + 8) * 32 + nt * 4 + tig] = lo;
        }
}

// ============================================================
// 3) Flash attention: cp.async double-buffered K/V, 1 barrier/iter, exp2 softmax
// ============================================================
#define FSTR 36
#define FQ_H 0
#define FQ_L 4608
#define FKV0 9216
#define KVBUF 9216
#define KH_O 0
#define KL_O 2304
#define VH_O 4608
#define VL_O 6912
#define FLASH_SMEM_BYTES ((FKV0 + 2*KVBUF) * 4)   // 110592

__global__ __launch_bounds__(256, 2) void flash_kernel() {
    extern __shared__ uint32_t fsm[];
    int t = threadIdx.x, w = t >> 5, lane = t & 31;
    int bh = blockIdx.y;
    int b = bh >> 4, h = bh & 15;
    int q0 = blockIdx.x * 128;
    int rb = w * 16;

    uint32_t sb = smem_to_u32(fsm);
    uint32_t oQ  = offA(rb, FSTR, lane);
    uint32_t oBf = offB(FSTR, lane);
    uint32_t aQh = sb + 4u * FQ_H + oQ;
    uint32_t aQl = sb + 4u * FQ_L + oQ;

    const uint32_t* qph = g_qs_hi + ((size_t)bh * SEQ + q0) * 32;
    const uint32_t* qpl = g_qs_lo + ((size_t)bh * SEQ + q0) * 32;
    const uint32_t* kph = g_kT_hi + (size_t)bh * SEQ * 32;
    const uint32_t* kpl = g_kT_lo + (size_t)bh * SEQ * 32;
    const uint32_t* vph = g_vt_hi + (size_t)bh * HD * (SEQ / 2);
    const uint32_t* vpl = g_vt_lo + (size_t)bh * HD * (SEQ / 2);

    // prefetch KV tile 0 (async) + stage Q (sync copies)
    {
        uint32_t base = sb + 4u * FKV0;
#pragma unroll
        for (int j = 0; j < 2; j++) {
            int u = j * 256 + t;
            int row = u >> 3, wq = (u & 7) * 4;
            uint32_t so = 4u * (row * FSTR + wq);
            cp16(base + 4u * KH_O + so, kph + (size_t)row * 32 + wq);
            cp16(base + 4u * KL_O + so, kpl + (size_t)row * 32 + wq);
            cp16(base + 4u * VH_O + so, vph + (size_t)row * (SEQ / 2) + wq);
            cp16(base + 4u * VL_O + so, vpl + (size_t)row * (SEQ / 2) + wq);
        }
        CP_COMMIT();
    }
    uint32_t* Qh = fsm + FQ_H;
    uint32_t* Ql = fsm + FQ_L;
#pragma unroll
    for (int j = 0; j < 4; j++) {
        int u = j * 256 + t;
        int row = u >> 3, wq = (u & 7) * 4;
        *(uint4*)&Qh[row * FSTR + wq] = *(const uint4*)&qph[row * 32 + wq];
        *(uint4*)&Ql[row * FSTR + wq] = *(const uint4*)&qpl[row * 32 + wq];
    }

    float m0 = -1e30f, m1 = -1e30f, l0 = 0.f, l1 = 0.f;
    float ctx[8][4];
#pragma unroll
    for (int nt = 0; nt < 8; nt++)
#pragma unroll
        for (int e = 0; e < 4; e++) ctx[nt][e] = 0.f;

    const int NT = SEQ / 64;
    for (int kt = 0; kt < NT; kt++) {
        int cur = kt & 1;
        CP_WAIT0();
        __syncthreads();    // KV(cur) visible; all warps past compute(kt-1)
        if (kt + 1 < NT) {  // prefetch next tile into other buffer
            uint32_t base = sb + 4u * (FKV0 + (cur ^ 1) * KVBUF);
            int kn = kt + 1;
#pragma unroll
            for (int j = 0; j < 2; j++) {
                int u = j * 256 + t;
                int row = u >> 3, wq = (u & 7) * 4;
                uint32_t so = 4u * (row * FSTR + wq);
                cp16(base + 4u * KH_O + so, kph + (size_t)(kn * 64 + row) * 32 + wq);
                cp16(base + 4u * KL_O + so, kpl + (size_t)(kn * 64 + row) * 32 + wq);
                cp16(base + 4u * VH_O + so, vph + (size_t)row * (SEQ / 2) + kn * 32 + wq);
                cp16(base + 4u * VL_O + so, vpl + (size_t)row * (SEQ / 2) + kn * 32 + wq);
            }
            CP_COMMIT();
        }
        uint32_t kvb = sb + 4u * (FKV0 + cur * KVBUF);
        uint32_t aKh = kvb + 4u * KH_O + oBf;
        uint32_t aKl = kvb + 4u * KL_O + oBf;
        uint32_t aVh = kvb + 4u * VH_O + oBf;
        uint32_t aVl = kvb + 4u * VL_O + oBf;

        // S = Q @ K^T (16x64 per warp), scores already in log2 domain
        float s[8][4];
#pragma unroll
        for (int nt = 0; nt < 8; nt++)
#pragma unroll
            for (int e = 0; e < 4; e++) s[nt][e] = 0.f;
#pragma unroll
        for (int ks = 0; ks < 4; ks++) {
            uint32_t qh4[4], ql4[4];
            ldsm_x4(qh4, aQh + ks * 32);
            ldsm_x4(ql4, aQl + ks * 32);
#pragma unroll
            for (int np = 0; np < 4; np++) {
                uint32_t kh4[4], kl4[4];
                ldsm_x4(kh4, aKh + np * (16 * FSTR * 4) + ks * 32);
                ldsm_x4(kl4, aKl + np * (16 * FSTR * 4) + ks * 32);
                mma3(s[2*np],   qh4, ql4, kh4[0], kh4[1], kl4[0], kl4[1]);
                mma3(s[2*np+1], qh4, ql4, kh4[2], kh4[3], kl4[2], kl4[3]);
            }
        }

        // online softmax (base-2)
        float rm0 = -1e30f, rm1 = -1e30f;
#pragma unroll
        for (int nt = 0; nt < 8; nt++) {
            rm0 = fmaxf(rm0, fmaxf(s[nt][0], s[nt][1]));
            rm1 = fmaxf(rm1, fmaxf(s[nt][2], s[nt][3]));
        }
        rm0 = fmaxf(rm0, __shfl_xor_sync(0xffffffffu, rm0, 1));
        rm0 = fmaxf(rm0, __shfl_xor_sync(0xffffffffu, rm0, 2));
        rm1 = fmaxf(rm1, __shfl_xor_sync(0xffffffffu, rm1, 1));
        rm1 = fmaxf(rm1, __shfl_xor_sync(0xffffffffu, rm1, 2));
        float mn0 = fmaxf(m0, rm0), mn1 = fmaxf(m1, rm1);
        float corr0 = ex2f(m0 - mn0), corr1 = ex2f(m1 - mn1);
        m0 = mn0; m1 = mn1;
        float rs0 = 0.f, rs1 = 0.f;
#pragma unroll
        for (int nt = 0; nt < 8; nt++) {
            s[nt][0] = ex2f(s[nt][0] - mn0); rs0 += s[nt][0];
            s[nt][1] = ex2f(s[nt][1] - mn0); rs0 += s[nt][1];
            s[nt][2] = ex2f(s[nt][2] - mn1); rs1 += s[nt][2];
            s[nt][3] = ex2f(s[nt][3] - mn1); rs1 += s[nt][3];
        }
        rs0 += __shfl_xor_sync(0xffffffffu, rs0, 1);
        rs0 += __shfl_xor_sync(0xffffffffu, rs0, 2);
        rs1 += __shfl_xor_sync(0xffffffffu, rs1, 1);
        rs1 += __shfl_xor_sync(0xffffffffu, rs1, 2);
        l0 = l0 * corr0 + rs0;
        l1 = l1 * corr1 + rs1;
#pragma unroll
        for (int nt = 0; nt < 8; nt++) {
            ctx[nt][0] *= corr0; ctx[nt][1] *= corr0;
            ctx[nt][2] *= corr1; ctx[nt][3] *= corr1;
        }

        // ctx += P @ V
#pragma unroll
        for (int ks = 0; ks < 4; ks++) {
            uint32_t ph[4], pl[4];
            split2(s[2*ks][0],   s[2*ks][1],   ph[0], pl[0]);
            split2(s[2*ks][2],   s[2*ks][3],   ph[1], pl[1]);
            split2(s[2*ks+1][0], s[2*ks+1][1], ph[2], pl[2]);
            split2(s[2*ks+1][2], s[2*ks+1][3], ph[3], pl[3]);
#pragma unroll
            for (int np = 0; np < 4; np++) {
                uint32_t vh4[4], vl4[4];
                ldsm_x4(vh4, aVh + np * (16 * FSTR * 4) + ks * 32);
                ldsm_x4(vl4, aVl + np * (16 * FSTR * 4) + ks * 32);
                mma3(ctx[2*np],   ph, pl, vh4[0], vh4[1], vl4[0], vl4[1]);
                mma3(ctx[2*np+1], ph, pl, vh4[2], vh4[3], vl4[2], vl4[3]);
            }
        }
    }

    int g = lane >> 2, tig = lane & 3;
    float invl0 = 1.0f / l0, invl1 = 1.0f / l1;
    int r0 = q0 + rb + g;
#pragma unroll
    for (int nt = 0; nt < 8; nt++) {
        int col = h * HD + nt * 8 + 2 * tig;
        *(float2*)(g_ctx + ((size_t)b * SEQ + r0) * DM + col) =
            make_float2(ctx[nt][0] * invl0, ctx[nt][1] * invl0);
        *(float2*)(g_ctx + ((size_t)b * SEQ + r0 + 8) * DM + col) =
            make_float2(ctx[nt][2] * invl1, ctx[nt][3] * invl1);
    }
}

// ============================================================
// 4) out = ctx @ out_w^T + out_b -- register-prefetch double-buffered
// ============================================================
__global__ __launch_bounds__(128) void out_mma_kernel(const float* __restrict__ wgt,
                                                      const float* __restrict__ bias,
                                                      float* __restrict__ out) {
    extern __shared__ uint32_t qsm[];
    int t = threadIdx.x, w = t >> 5, lane = t & 31;
    int g = lane >> 2, tig = lane & 3;
    int row0 = blockIdx.x * 128;
    int col0 = blockIdx.y * 64;
    const float* Ap = g_ctx + (size_t)row0 * DM;
    const float* Bp = wgt   + (size_t)col0 * DM;

    uint32_t sb = smem_to_u32(qsm);
    uint32_t oA = offA(w * 32, GSTR, lane);
    uint32_t oBf = offB(GSTR, lane);

    float acc[2][8][4];
#pragma unroll
    for (int mt = 0; mt < 2; mt++)
#pragma unroll
        for (int nt = 0; nt < 8; nt++)
#pragma unroll
            for (int e = 0; e < 4; e++) acc[mt][nt][e] = 0.f;

    float4 aR[8], bR[4];
#pragma unroll
    for (int j = 0; j < 8; j++) {
        int idx = j * 128 + t;
        int row = idx >> 3, kg = idx & 7;
        aR[j] = *(const float4*)(Ap + (size_t)row * DM + kg * 4);
    }
#pragma unroll
    for (int j = 0; j < 4; j++) {
        int idx = j * 128 + t;
        int n = idx >> 3, kg = idx & 7;
        bR[j] = *(const float4*)(Bp + (size_t)n * DM + kg * 4);
    }

    const int NC = DM / 32;
    for (int c = 0; c < NC; c++) {
        int cur = c & 1;
        uint32_t* Ah = qsm + cur * QBUF + QA_H;
        uint32_t* Al = qsm + cur * QBUF + QA_L;
        uint32_t* Bh = qsm + cur * QBUF + QB_H;
        uint32_t* Bl = qsm + cur * QBUF + QB_L;
#pragma unroll
        for (int j = 0; j < 8; j++) {
            int idx = j * 128 + t;
            int row = idx >> 3, kg = idx & 7;
            uint32_t h2[2], l2[2]; split4(aR[j], h2, l2);
            Ah[row * GSTR + kg * 2] = h2[0]; Ah[row * GSTR + kg * 2 + 1] = h2[1];
            Al[row * GSTR + kg * 2] = l2[0]; Al[row * GSTR + kg * 2 + 1] = l2[1];
        }
#pragma unroll
        for (int j = 0; j < 4; j++) {
            int idx = j * 128 + t;
            int n = idx >> 3, kg = idx & 7;
            uint32_t h2[2], l2[2]; split4(bR[j], h2, l2);
            Bh[n * GSTR + kg * 2] = h2[0]; Bh[n * GSTR + kg * 2 + 1] = h2[1];
            Bl[n * GSTR + kg * 2] = l2[0]; Bl[n * GSTR + kg * 2 + 1] = l2[1];
        }
        __syncthreads();
        if (c + 1 < NC) {
            int k0 = (c + 1) * 32;
#pragma unroll
            for (int j = 0; j < 8; j++) {
                int idx = j * 128 + t;
                int row = idx >> 3, kg = idx & 7;
                aR[j] = *(const float4*)(Ap + (size_t)row * DM + k0 + kg * 4);
            }
#pragma unroll
            for (int j = 0; j < 4; j++) {
                int idx = j * 128 + t;
                int n = idx >> 3, kg = idx & 7;
                bR[j] = *(const float4*)(Bp + (size_t)n * DM + k0 + kg * 4);
            }
        }
        uint32_t aAh = sb + 4u * (cur * QBUF + QA_H) + oA;
        uint32_t aAl = sb + 4u * (cur * QBUF + QA_L) + oA;
        uint32_t aBh = sb + 4u * (cur * QBUF + QB_H) + oBf;
        uint32_t aBl = sb + 4u * (cur * QBUF + QB_L) + oBf;
#pragma unroll
        for (int ks = 0; ks < 2; ks++) {
            uint32_t ah[2][4], al[2][4];
            ldsm_x4(ah[0], aAh + ks * 32);
            ldsm_x4(ah[1], aAh + 16 * GSTR * 4 + ks * 32);
            ldsm_x4(al[0], aAl + ks * 32);
            ldsm_x4(al[1], aAl + 16 * GSTR * 4 + ks * 32);
#pragma unroll
            for (int np = 0; np < 4; np++) {
                uint32_t kh4[4], kl4[4];
                ldsm_x4(kh4, aBh + np * (16 * GSTR * 4) + ks * 32);
                ldsm_x4(kl4, aBl + np * (16 * GSTR * 4) + ks * 32);
                mma3(acc[0][2*np],   ah[0], al[0], kh4[0], kh4[1], kl4[0], kl4[1]);
                mma3(acc[0][2*np+1], ah[0], al[0], kh4[2], kh4[3], kl4[2], kl4[3]);
                mma3(acc[1][2*np],   ah[1], al[1], kh4[0], kh4[1], kl4[0], kl4[1]);
                mma3(acc[1][2*np+1], ah[1], al[1], kh4[2], kh4[3], kl4[2], kl4[3]);
            }
        }
    }
#pragma unroll
    for (int mt = 0; mt < 2; mt++)
#pragma unroll
        for (int nt = 0; nt < 8; nt++) {
            int col = col0 + nt * 8 + 2 * tig;
            size_t r0 = row0 + w * 32 + mt * 16 + g;
            float2 bi = *(const float2*)(bias + col);
            *(float2*)(out + r0 * DM + col) =
                make_float2(acc[mt][nt][0] + bi.x, acc[mt][nt][1] + bi.y);
            *(float2*)(out + (r0 + 8) * DM + col) =
                make_float2(acc[mt][nt][2] + bi.x, acc[mt][nt][3] + bi.y);
        }
}

// ============================================================
extern "C" void kernel_launch(void* const* d_in, const int* in_sizes, int n_in,
                              void* d_out, int out_size) {
    (void)in_sizes; (void)n_in; (void)out_size;
    const float* q    = (const float*)d_in[0];
    const float* k    = (const float*)d_in[1];
    const float* v    = (const float*)d_in[2];
    const float* mask = (const float*)d_in[3];
    const float* ow   = (const float*)d_in[4];
    const float* ob   = (const float*)d_in[5];
    float* out = (float*)d_out;

    cudaFuncSetAttribute(flash_kernel, cudaFuncAttributeMaxDynamicSharedMemorySize,
                         FLASH_SMEM_BYTES);
    cudaFuncSetAttribute(qt_mma_kernel, cudaFuncAttributeMaxDynamicSharedMemorySize,
                         QT_SMEM_BYTES);
    cudaFuncSetAttribute(out_mma_kernel, cudaFuncAttributeMaxDynamicSharedMemorySize,
                         QT_SMEM_BYTES);

    rope_kernel<<<dim3(SEQ / 32, BH), 256>>>(q, k);
    vT_kernel<<<dim3(SEQ / 64, BH), 256>>>(v);
    qt_mma_kernel<<<dim3(SEQ / 128, BH), 128, QT_SMEM_BYTES>>>(mask);
    flash_kernel<<<dim3(SEQ / 128, BH), 256, FLASH_SMEM_BYTES>>>();
    out_mma_kernel<<<dim3(NB * SEQ / 128, DM / 64), 128, QT_SMEM_BYTES>>>(ow, ob, out);
}

// round 8
// speedup vs baseline: 2.9343x; 1.0285x over previous
#include <cuda_runtime.h>
#include <math.h>
#include <cstdint>

#define NB   2
#define NH   16
#define BH   (NB*NH)
#define SEQ  2048
#define HD   64
#define DM   1024
#define SCALE 0.125f
#define LOG2E 1.4426950408889634f

// ---- scratch (device globals; no allocation APIs allowed) ----
__device__ __align__(16) uint32_t g_qrT_hi[BH*HD*(SEQ/2)];
__device__ __align__(16) uint32_t g_qrT_lo[BH*HD*(SEQ/2)];
__device__ __align__(16) uint32_t g_kT_hi [BH*SEQ*(HD/2)];
__device__ __align__(16) uint32_t g_kT_lo [BH*SEQ*(HD/2)];
__device__ __align__(16) uint32_t g_vt_hi [BH*HD*(SEQ/2)];
__device__ __align__(16) uint32_t g_vt_lo [BH*HD*(SEQ/2)];
__device__ __align__(16) uint32_t g_qs_hi [BH*SEQ*(HD/2)];
__device__ __align__(16) uint32_t g_qs_lo [BH*SEQ*(HD/2)];
__device__ float g_ctx[NB*SEQ*DM];

// ================= split-bf16 helpers =================
__device__ __forceinline__ void split2(float x, float y, uint32_t& hi, uint32_t& lo) {
    uint32_t h;
    asm("cvt.rn.bf16x2.f32 %0, %1, %2;" : "=r"(h) : "f"(y), "f"(x));
    float hx = __uint_as_float(h << 16);
    float hy = __uint_as_float(h & 0xFFFF0000u);
    asm("cvt.rn.bf16x2.f32 %0, %1, %2;" : "=r"(lo) : "f"(y - hy), "f"(x - hx));
    hi = h;
}
__device__ __forceinline__ void split4(float4 a, uint32_t* h2, uint32_t* l2) {
    split2(a.x, a.y, h2[0], l2[0]);
    split2(a.z, a.w, h2[1], l2[1]);
}
__device__ __forceinline__ void mma_bf16(float* c,
        uint32_t a0, uint32_t a1, uint32_t a2, uint32_t a3, uint32_t b0, uint32_t b1) {
    asm volatile("mma.sync.aligned.m16n8k16.row.col.f32.bf16.bf16.f32 "
                 "{%0,%1,%2,%3}, {%4,%5,%6,%7}, {%8,%9}, {%0,%1,%2,%3};"
                 : "+f"(c[0]), "+f"(c[1]), "+f"(c[2]), "+f"(c[3])
                 : "r"(a0), "r"(a1), "r"(a2), "r"(a3), "r"(b0), "r"(b1));
}
__device__ __forceinline__ void mma3(float* c, const uint32_t* ah, const uint32_t* al,
                                     uint32_t bh0, uint32_t bh1, uint32_t bl0, uint32_t bl1) {
    mma_bf16(c, ah[0], ah[1], ah[2], ah[3], bh0, bh1);
    mma_bf16(c, ah[0], ah[1], ah[2], ah[3], bl0, bl1);
    mma_bf16(c, al[0], al[1], al[2], al[3], bh0, bh1);
}

// ================= ldmatrix / cp.async / misc =================
__device__ __forceinline__ void ldsm_x4(uint32_t* r, uint32_t a) {
    asm volatile("ldmatrix.sync.aligned.m8n8.x4.shared.b16 {%0,%1,%2,%3}, [%4];"
                 : "=r"(r[0]), "=r"(r[1]), "=r"(r[2]), "=r"(r[3]) : "r"(a));
}
__device__ __forceinline__ uint32_t smem_to_u32(const void* p) {
    uint32_t a;
    asm("{ .reg .u64 t; cvta.to.shared.u64 t, %1; cvt.u32.u64 %0, t; }" : "=r"(a) : "l"(p));
    return a;
}
__device__ __forceinline__ void cp16(uint32_t saddr, const void* g) {
    asm volatile("cp.async.cg.shared.global [%0], [%1], 16;" :: "r"(saddr), "l"(g));
}
#define CP_COMMIT() asm volatile("cp.async.commit_group;" ::: "memory")
#define CP_WAIT0()  asm volatile("cp.async.wait_group 0;" ::: "memory")
__device__ __forceinline__ float ex2f(float x) {
    float y; asm("ex2.approx.f32 %0, %1;" : "=f"(y) : "f"(x)); return y;
}
__device__ __forceinline__ uint32_t offA(int rb, int stride, int lane) {
    return 4u * ((uint32_t)(rb + (lane & 15)) * stride + ((lane >> 4) & 1) * 4);
}
__device__ __forceinline__ uint32_t offB(int stride, int lane) {
    return 4u * ((uint32_t)((lane & 7) + ((lane >> 4) & 1) * 8) * stride
                 + ((lane >> 3) & 1) * 4);
}

// ============================================================
// 1) RoPE
// ============================================================
__global__ __launch_bounds__(256) void rope_kernel(const float* __restrict__ q,
                                                   const float* __restrict__ k) {
    __shared__ float qs[64][33];
    __shared__ float ks2[32][66];
    int t = threadIdx.x;
    int bh = blockIdx.y;
    int s0 = blockIdx.x * 32;
    int d  = t & 31;
    float inv_freq = 1.0f / powf(10000.0f, (float)(2 * d) * (1.0f / 64.0f));
#pragma unroll
    for (int j = 0; j < 4; j++) {
        int sl = j * 8 + (t >> 5);
        int s = s0 + sl;
        float sn, cs;
        sincosf((float)s * inv_freq, &sn, &cs);
        size_t base = ((size_t)bh * SEQ + s) * HD;
        float a1 = q[base + d], a2 = q[base + d + 32];
        qs[d][sl]      = a1 * cs - a2 * sn;
        qs[d + 32][sl] = a2 * cs + a1 * sn;
        float b1 = k[base + d], b2 = k[base + d + 32];
        ks2[sl][d]      = b1 * cs - b2 * sn;
        ks2[sl][d + 32] = b2 * cs + b1 * sn;
    }
    __syncthreads();
#pragma unroll
    for (int j = 0; j < 4; j++) {
        int idx = j * 256 + t;
        int dd = idx >> 4, sp = idx & 15;
        uint32_t hi, lo;
        split2(qs[dd][2 * sp], qs[dd][2 * sp + 1], hi, lo);
        size_t o = ((size_t)bh * HD + dd) * (SEQ / 2) + s0 / 2 + sp;
        g_qrT_hi[o] = hi; g_qrT_lo[o] = lo;
    }
#pragma unroll
    for (int j = 0; j < 4; j++) {
        int idx = j * 256 + t;
        int sl = idx >> 5, w = idx & 31;
        uint32_t hi, lo;
        split2(ks2[sl][2 * w], ks2[sl][2 * w + 1], hi, lo);
        size_t o = ((size_t)bh * SEQ + s0 + sl) * 32 + w;
        g_kT_hi[o] = hi; g_kT_lo[o] = lo;
    }
}

// ============================================================
// 1b) V transpose
// ============================================================
__global__ __launch_bounds__(256) void vT_kernel(const float* __restrict__ v) {
    __shared__ float vs[64][65];
    int t = threadIdx.x;
    int bh = blockIdx.y;
    int s0 = blockIdx.x * 64;
#pragma unroll
    for (int j = 0; j < 16; j++) {
        int idx = j * 256 + t;
        int sl = idx >> 6, d = idx & 63;
        vs[sl][d] = v[((size_t)bh * SEQ + s0 + sl) * HD + d];
    }
    __syncthreads();
#pragma unroll
    for (int j = 0; j < 8; j++) {
        int idx = j * 256 + t;
        int d = idx >> 5, sp = idx & 31;
        uint32_t hi, lo;
        split2(vs[2 * sp][d], vs[2 * sp + 1][d], hi, lo);
        size_t o = ((size_t)bh * HD + d) * (SEQ / 2) + s0 / 2 + sp;
        g_vt_hi[o] = hi; g_vt_lo[o] = lo;
    }
}

// ============================================================
// 2) qt = W[h] @ qr -- register-prefetch double-buffered (unchanged)
// ============================================================
#define GSTR 20
#define QA_H 0
#define QA_L 2560
#define QB_H 5120
#define QB_L 6400
#define QBUF 7680
#define QT_SMEM_BYTES (2*QBUF*4)

__global__ __launch_bounds__(128) void qt_mma_kernel(const float* __restrict__ mask) {
    extern __shared__ uint32_t qsm[];
    int t = threadIdx.x, w = t >> 5, lane = t & 31;
    int g = lane >> 2, tig = lane & 3;
    int yb = blockIdx.y;
    int h = yb >> 1, b = yb & 1;
    int bh = b * NH + h;
    int row0 = blockIdx.x * 128;
    const float* Ap = mask + (size_t)h * SEQ * SEQ + (size_t)row0 * SEQ;
    const uint32_t* Bph = g_qrT_hi + (size_t)bh * HD * (SEQ / 2);
    const uint32_t* Bpl = g_qrT_lo + (size_t)bh * HD * (SEQ / 2);

    uint32_t sb = smem_to_u32(qsm);
    uint32_t oA = offA(w * 32, GSTR, lane);
    uint32_t oBf = offB(GSTR, lane);

    float acc[2][8][4];
#pragma unroll
    for (int mt = 0; mt < 2; mt++)
#pragma unroll
        for (int nt = 0; nt < 8; nt++)
#pragma unroll
            for (int e = 0; e < 4; e++) acc[mt][nt][e] = 0.f;

    float4 aR[8]; uint4 bhR[2], blR[2];
#pragma unroll
    for (int j = 0; j < 8; j++) {
        int idx = j * 128 + t;
        int row = idx >> 3, kg = idx & 7;
        aR[j] = *(const float4*)(Ap + (size_t)row * SEQ + kg * 4);
    }
#pragma unroll
    for (int j = 0; j < 2; j++) {
        int u = j * 128 + t;
        int row = u >> 2, wq = (u & 3) * 4;
        bhR[j] = *(const uint4*)&Bph[(size_t)row * (SEQ / 2) + wq];
        blR[j] = *(const uint4*)&Bpl[(size_t)row * (SEQ / 2) + wq];
    }

    const int NC = SEQ / 32;
    for (int c = 0; c < NC; c++) {
        int cur = c & 1;
        uint32_t* Ah = qsm + cur * QBUF + QA_H;
        uint32_t* Al = qsm + cur * QBUF + QA_L;
        uint32_t* Bh = qsm + cur * QBUF + QB_H;
        uint32_t* Bl = qsm + cur * QBUF + QB_L;
#pragma unroll
        for (int j = 0; j < 8; j++) {
            int idx = j * 128 + t;
            int row = idx >> 3, kg = idx & 7;
            uint32_t h2[2], l2[2]; split4(aR[j], h2, l2);
            Ah[row * GSTR + kg * 2] = h2[0]; Ah[row * GSTR + kg * 2 + 1] = h2[1];
            Al[row * GSTR + kg * 2] = l2[0]; Al[row * GSTR + kg * 2 + 1] = l2[1];
        }
#pragma unroll
        for (int j = 0; j < 2; j++) {
            int u = j * 128 + t;
            int row = u >> 2, wq = (u & 3) * 4;
            *(uint4*)&Bh[row * GSTR + wq] = bhR[j];
            *(uint4*)&Bl[row * GSTR + wq] = blR[j];
        }
        __syncthreads();
        if (c + 1 < NC) {
            int k0 = (c + 1) * 32;
#pragma unroll
            for (int j = 0; j < 8; j++) {
                int idx = j * 128 + t;
                int row = idx >> 3, kg = idx & 7;
                aR[j] = *(const float4*)(Ap + (size_t)row * SEQ + k0 + kg * 4);
            }
#pragma unroll
            for (int j = 0; j < 2; j++) {
                int u = j * 128 + t;
                int row = u >> 2, wq = (u & 3) * 4;
                bhR[j] = *(const uint4*)&Bph[(size_t)row * (SEQ / 2) + k0 / 2 + wq];
                blR[j] = *(const uint4*)&Bpl[(size_t)row * (SEQ / 2) + k0 / 2 + wq];
            }
        }
        uint32_t aAh = sb + 4u * (cur * QBUF + QA_H) + oA;
        uint32_t aAl = sb + 4u * (cur * QBUF + QA_L) + oA;
        uint32_t aBh = sb + 4u * (cur * QBUF + QB_H) + oBf;
        uint32_t aBl = sb + 4u * (cur * QBUF + QB_L) + oBf;
#pragma unroll
        for (int ks = 0; ks < 2; ks++) {
            uint32_t ah[2][4], al[2][4];
            ldsm_x4(ah[0], aAh + ks * 32);
            ldsm_x4(ah[1], aAh + 16 * GSTR * 4 + ks * 32);
            ldsm_x4(al[0], aAl + ks * 32);
            ldsm_x4(al[1], aAl + 16 * GSTR * 4 + ks * 32);
#pragma unroll
            for (int np = 0; np < 4; np++) {
                uint32_t kh4[4], kl4[4];
                ldsm_x4(kh4, aBh + np * (16 * GSTR * 4) + ks * 32);
                ldsm_x4(kl4, aBl + np * (16 * GSTR * 4) + ks * 32);
                mma3(acc[0][2*np],   ah[0], al[0], kh4[0], kh4[1], kl4[0], kl4[1]);
                mma3(acc[0][2*np+1], ah[0], al[0], kh4[2], kh4[3], kl4[2], kl4[3]);
                mma3(acc[1][2*np],   ah[1], al[1], kh4[0], kh4[1], kl4[0], kl4[1]);
                mma3(acc[1][2*np+1], ah[1], al[1], kh4[2], kh4[3], kl4[2], kl4[3]);
            }
        }
    }
    const float SC = SCALE * LOG2E;
    size_t ro = (size_t)bh * SEQ + row0;
#pragma unroll
    for (int mt = 0; mt < 2; mt++)
#pragma unroll
        for (int nt = 0; nt < 8; nt++) {
            uint32_t hi, lo;
            size_t r0 = ro + w * 32 + mt * 16 + g;
            split2(acc[mt][nt][0] * SC, acc[mt][nt][1] * SC, hi, lo);
            g_qs_hi[r0 * 32 + nt * 4 + tig] = hi;
            g_qs_lo[r0 * 32 + nt * 4 + tig] = lo;
            split2(acc[mt][nt][2] * SC, acc[mt][nt][3] * SC, hi, lo);
            g_qs_hi[(r0 + 8) * 32 + nt * 4 + tig] = hi;
            g_qs_lo[(r0 + 8) * 32 + nt * 4 + tig] = lo;
        }
}

// ============================================================
// 3) Flash: 4 warps x 32 q-rows (K/V fragments shared by 2 m-tiles)
// ============================================================
#define FSTR 36
#define FQ_H 0
#define FQ_L 4608
#define FKV0 9216
#define KVBUF 9216
#define KH_O 0
#define KL_O 2304
#define VH_O 4608
#define VL_O 6912
#define FLASH_SMEM_BYTES ((FKV0 + 2*KVBUF) * 4)   // 110592

__global__ __launch_bounds__(128, 2) void flash_kernel() {
    extern __shared__ uint32_t fsm[];
    int t = threadIdx.x, w = t >> 5, lane = t & 31;
    int bh = blockIdx.y;
    int b = bh >> 4, h = bh & 15;
    int q0 = blockIdx.x * 128;
    int rb = w * 32;                      // 32 q-rows per warp

    uint32_t sb = smem_to_u32(fsm);
    uint32_t oQ  = offA(rb, FSTR, lane);
    uint32_t oBf = offB(FSTR, lane);
    uint32_t aQh = sb + 4u * FQ_H + oQ;
    uint32_t aQl = sb + 4u * FQ_L + oQ;

    const uint32_t* qph = g_qs_hi + ((size_t)bh * SEQ + q0) * 32;
    const uint32_t* qpl = g_qs_lo + ((size_t)bh * SEQ + q0) * 32;
    const uint32_t* kph = g_kT_hi + (size_t)bh * SEQ * 32;
    const uint32_t* kpl = g_kT_lo + (size_t)bh * SEQ * 32;
    const uint32_t* vph = g_vt_hi + (size_t)bh * HD * (SEQ / 2);
    const uint32_t* vpl = g_vt_lo + (size_t)bh * HD * (SEQ / 2);

    // prefetch KV tile 0 (async)
    {
        uint32_t base = sb + 4u * FKV0;
#pragma unroll
        for (int j = 0; j < 4; j++) {
            int u = j * 128 + t;
            int row = u >> 3, wq = (u & 7) * 4;
            uint32_t so = 4u * (row * FSTR + wq);
            cp16(base + 4u * KH_O + so, kph + (size_t)row * 32 + wq);
            cp16(base + 4u * KL_O + so, kpl + (size_t)row * 32 + wq);
            cp16(base + 4u * VH_O + so, vph + (size_t)row * (SEQ / 2) + wq);
            cp16(base + 4u * VL_O + so, vpl + (size_t)row * (SEQ / 2) + wq);
        }
        CP_COMMIT();
    }
    // stage Q (sync copies)
    uint32_t* Qh = fsm + FQ_H;
    uint32_t* Ql = fsm + FQ_L;
#pragma unroll
    for (int j = 0; j < 8; j++) {
        int u = j * 128 + t;
        int row = u >> 3, wq = (u & 7) * 4;
        *(uint4*)&Qh[row * FSTR + wq] = *(const uint4*)&qph[row * 32 + wq];
        *(uint4*)&Ql[row * FSTR + wq] = *(const uint4*)&qpl[row * 32 + wq];
    }

    float m[2][2], l[2][2];
    float ctx[2][8][4];
#pragma unroll
    for (int mt = 0; mt < 2; mt++) {
        m[mt][0] = -1e30f; m[mt][1] = -1e30f;
        l[mt][0] = 0.f;    l[mt][1] = 0.f;
#pragma unroll
        for (int nt = 0; nt < 8; nt++)
#pragma unroll
            for (int e = 0; e < 4; e++) ctx[mt][nt][e] = 0.f;
    }

    const int NT = SEQ / 64;
    for (int kt = 0; kt < NT; kt++) {
        int cur = kt & 1;
        CP_WAIT0();
        __syncthreads();
        if (kt + 1 < NT) {
            uint32_t base = sb + 4u * (FKV0 + (cur ^ 1) * KVBUF);
            int kn = kt + 1;
#pragma unroll
            for (int j = 0; j < 4; j++) {
                int u = j * 128 + t;
                int row = u >> 3, wq = (u & 7) * 4;
                uint32_t so = 4u * (row * FSTR + wq);
                cp16(base + 4u * KH_O + so, kph + (size_t)(kn * 64 + row) * 32 + wq);
                cp16(base + 4u * KL_O + so, kpl + (size_t)(kn * 64 + row) * 32 + wq);
                cp16(base + 4u * VH_O + so, vph + (size_t)row * (SEQ / 2) + kn * 32 + wq);
                cp16(base + 4u * VL_O + so, vpl + (size_t)row * (SEQ / 2) + kn * 32 + wq);
            }
            CP_COMMIT();
        }
        uint32_t kvb = sb + 4u * (FKV0 + cur * KVBUF);
        uint32_t aKh = kvb + 4u * KH_O + oBf;
        uint32_t aKl = kvb + 4u * KL_O + oBf;
        uint32_t aVh = kvb + 4u * VH_O + oBf;
        uint32_t aVl = kvb + 4u * VL_O + oBf;

        // S = Q @ K^T : 32x64 per warp, K fragments shared across m-tiles
        float s[2][8][4];
#pragma unroll
        for (int mt = 0; mt < 2; mt++)
#pragma unroll
            for (int nt = 0; nt < 8; nt++)
#pragma unroll
                for (int e = 0; e < 4; e++) s[mt][nt][e] = 0.f;
#pragma unroll
        for (int ks = 0; ks < 4; ks++) {
            uint32_t qh[2][4], ql[2][4];
            ldsm_x4(qh[0], aQh + ks * 32);
            ldsm_x4(ql[0], aQl + ks * 32);
            ldsm_x4(qh[1], aQh + 16 * FSTR * 4 + ks * 32);
            ldsm_x4(ql[1], aQl + 16 * FSTR * 4 + ks * 32);
#pragma unroll
            for (int np = 0; np < 4; np++) {
                uint32_t kh4[4], kl4[4];
                ldsm_x4(kh4, aKh + np * (16 * FSTR * 4) + ks * 32);
                ldsm_x4(kl4, aKl + np * (16 * FSTR * 4) + ks * 32);
                mma3(s[0][2*np],   qh[0], ql[0], kh4[0], kh4[1], kl4[0], kl4[1]);
                mma3(s[0][2*np+1], qh[0], ql[0], kh4[2], kh4[3], kl4[2], kl4[3]);
                mma3(s[1][2*np],   qh[1], ql[1], kh4[0], kh4[1], kl4[0], kl4[1]);
                mma3(s[1][2*np+1], qh[1], ql[1], kh4[2], kh4[3], kl4[2], kl4[3]);
            }
        }

        // online softmax (base-2), per m-tile
#pragma unroll
        for (int mt = 0; mt < 2; mt++) {
            float rm0 = -1e30f, rm1 = -1e30f;
#pragma unroll
            for (int nt = 0; nt < 8; nt++) {
                rm0 = fmaxf(rm0, fmaxf(s[mt][nt][0], s[mt][nt][1]));
                rm1 = fmaxf(rm1, fmaxf(s[mt][nt][2], s[mt][nt][3]));
            }
            rm0 = fmaxf(rm0, __shfl_xor_sync(0xffffffffu, rm0, 1));
            rm0 = fmaxf(rm0, __shfl_xor_sync(0xffffffffu, rm0, 2));
            rm1 = fmaxf(rm1, __shfl_xor_sync(0xffffffffu, rm1, 1));
            rm1 = fmaxf(rm1, __shfl_xor_sync(0xffffffffu, rm1, 2));
            float mn0 = fmaxf(m[mt][0], rm0), mn1 = fmaxf(m[mt][1], rm1);
            float corr0 = ex2f(m[mt][0] - mn0), corr1 = ex2f(m[mt][1] - mn1);
            m[mt][0] = mn0; m[mt][1] = mn1;
            float rs0 = 0.f, rs1 = 0.f;
#pragma unroll
            for (int nt = 0; nt < 8; nt++) {
                s[mt][nt][0] = ex2f(s[mt][nt][0] - mn0); rs0 += s[mt][nt][0];
                s[mt][nt][1] = ex2f(s[mt][nt][1] - mn0); rs0 += s[mt][nt][1];
                s[mt][nt][2] = ex2f(s[mt][nt][2] - mn1); rs1 += s[mt][nt][2];
                s[mt][nt][3] = ex2f(s[mt][nt][3] - mn1); rs1 += s[mt][nt][3];
            }
            rs0 += __shfl_xor_sync(0xffffffffu, rs0, 1);
            rs0 += __shfl_xor_sync(0xffffffffu, rs0, 2);
            rs1 += __shfl_xor_sync(0xffffffffu, rs1, 1);
            rs1 += __shfl_xor_sync(0xffffffffu, rs1, 2);
            l[mt][0] = l[mt][0] * corr0 + rs0;
            l[mt][1] = l[mt][1] * corr1 + rs1;
#pragma unroll
            for (int nt = 0; nt < 8; nt++) {
                ctx[mt][nt][0] *= corr0; ctx[mt][nt][1] *= corr0;
                ctx[mt][nt][2] *= corr1; ctx[mt][nt][3] *= corr1;
            }
        }

        // ctx += P @ V : V fragments shared across m-tiles
#pragma unroll
        for (int ks = 0; ks < 4; ks++) {
            uint32_t ph[2][4], pl[2][4];
#pragma unroll
            for (int mt = 0; mt < 2; mt++) {
                split2(s[mt][2*ks][0],   s[mt][2*ks][1],   ph[mt][0], pl[mt][0]);
                split2(s[mt][2*ks][2],   s[mt][2*ks][3],   ph[mt][1], pl[mt][1]);
                split2(s[mt][2*ks+1][0], s[mt][2*ks+1][1], ph[mt][2], pl[mt][2]);
                split2(s[mt][2*ks+1][2], s[mt][2*ks+1][3], ph[mt][3], pl[mt][3]);
            }
#pragma unroll
            for (int np = 0; np < 4; np++) {
                uint32_t vh4[4], vl4[4];
                ldsm_x4(vh4, aVh + np * (16 * FSTR * 4) + ks * 32);
                ldsm_x4(vl4, aVl + np * (16 * FSTR * 4) + ks * 32);
                mma3(ctx[0][2*np],   ph[0], pl[0], vh4[0], vh4[1], vl4[0], vl4[1]);
                mma3(ctx[0][2*np+1], ph[0], pl[0], vh4[2], vh4[3], vl4[2], vl4[3]);
                mma3(ctx[1][2*np],   ph[1], pl[1], vh4[0], vh4[1], vl4[0], vl4[1]);
                mma3(ctx[1][2*np+1], ph[1], pl[1], vh4[2], vh4[3], vl4[2], vl4[3]);
            }
        }
    }

    int g = lane >> 2, tig = lane & 3;
#pragma unroll
    for (int mt = 0; mt < 2; mt++) {
        float invl0 = 1.0f / l[mt][0], invl1 = 1.0f / l[mt][1];
        int r0 = q0 + rb + mt * 16 + g;
#pragma unroll
        for (int nt = 0; nt < 8; nt++) {
            int col = h * HD + nt * 8 + 2 * tig;
            *(float2*)(g_ctx + ((size_t)b * SEQ + r0) * DM + col) =
                make_float2(ctx[mt][nt][0] * invl0, ctx[mt][nt][1] * invl0);
            *(float2*)(g_ctx + ((size_t)b * SEQ + r0 + 8) * DM + col) =
                make_float2(ctx[mt][nt][2] * invl1, ctx[mt][nt][3] * invl1);
        }
    }
}

// ============================================================
// 4) out = ctx @ out_w^T + out_b (unchanged)
// ============================================================
__global__ __launch_bounds__(128) void out_mma_kernel(const float* __restrict__ wgt,
                                                      const float* __restrict__ bias,
                                                      float* __restrict__ out) {
    extern __shared__ uint32_t qsm[];
    int t = threadIdx.x, w = t >> 5, lane = t & 31;
    int g = lane >> 2, tig = lane & 3;
    int row0 = blockIdx.x * 128;
    int col0 = blockIdx.y * 64;
    const float* Ap = g_ctx + (size_t)row0 * DM;
    const float* Bp = wgt   + (size_t)col0 * DM;

    uint32_t sb = smem_to_u32(qsm);
    uint32_t oA = offA(w * 32, GSTR, lane);
    uint32_t oBf = offB(GSTR, lane);

    float acc[2][8][4];
#pragma unroll
    for (int mt = 0; mt < 2; mt++)
#pragma unroll
        for (int nt = 0; nt < 8; nt++)
#pragma unroll
            for (int e = 0; e < 4; e++) acc[mt][nt][e] = 0.f;

    float4 aR[8], bR[4];
#pragma unroll
    for (int j = 0; j < 8; j++) {
        int idx = j * 128 + t;
        int row = idx >> 3, kg = idx & 7;
        aR[j] = *(const float4*)(Ap + (size_t)row * DM + kg * 4);
    }
#pragma unroll
    for (int j = 0; j < 4; j++) {
        int idx = j * 128 + t;
        int n = idx >> 3, kg = idx & 7;
        bR[j] = *(const float4*)(Bp + (size_t)n * DM + kg * 4);
    }

    const int NC = DM / 32;
    for (int c = 0; c < NC; c++) {
        int cur = c & 1;
        uint32_t* Ah = qsm + cur * QBUF + QA_H;
        uint32_t* Al = qsm + cur * QBUF + QA_L;
        uint32_t* Bh = qsm + cur * QBUF + QB_H;
        uint32_t* Bl = qsm + cur * QBUF + QB_L;
#pragma unroll
        for (int j = 0; j < 8; j++) {
            int idx = j * 128 + t;
            int row = idx >> 3, kg = idx & 7;
            uint32_t h2[2], l2[2]; split4(aR[j], h2, l2);
            Ah[row * GSTR + kg * 2] = h2[0]; Ah[row * GSTR + kg * 2 + 1] = h2[1];
            Al[row * GSTR + kg * 2] = l2[0]; Al[row * GSTR + kg * 2 + 1] = l2[1];
        }
#pragma unroll
        for (int j = 0; j < 4; j++) {
            int idx = j * 128 + t;
            int n = idx >> 3, kg = idx & 7;
            uint32_t h2[2], l2[2]; split4(bR[j], h2, l2);
            Bh[n * GSTR + kg * 2] = h2[0]; Bh[n * GSTR + kg * 2 + 1] = h2[1];
            Bl[n * GSTR + kg * 2] = l2[0]; Bl[n * GSTR + kg * 2 + 1] = l2[1];
        }
        __syncthreads();
        if (c + 1 < NC) {
            int k0 = (c + 1) * 32;
#pragma unroll
            for (int j = 0; j < 8; j++) {
                int idx = j * 128 + t;
                int row = idx >> 3, kg = idx & 7;
                aR[j] = *(const float4*)(Ap + (size_t)row * DM + k0 + kg * 4);
            }
#pragma unroll
            for (int j = 0; j < 4; j++) {
                int idx = j * 128 + t;
                int n = idx >> 3, kg = idx & 7;
                bR[j] = *(const float4*)(Bp + (size_t)n * DM + k0 + kg * 4);
            }
        }
        uint32_t aAh = sb + 4u * (cur * QBUF + QA_H) + oA;
        uint32_t aAl = sb + 4u * (cur * QBUF + QA_L) + oA;
        uint32_t aBh = sb + 4u * (cur * QBUF + QB_H) + oBf;
        uint32_t aBl = sb + 4u * (cur * QBUF + QB_L) + oBf;
#pragma unroll
        for (int ks = 0; ks < 2; ks++) {
            uint32_t ah[2][4], al[2][4];
            ldsm_x4(ah[0], aAh + ks * 32);
            ldsm_x4(ah[1], aAh + 16 * GSTR * 4 + ks * 32);
            ldsm_x4(al[0], aAl + ks * 32);
            ldsm_x4(al[1], aAl + 16 * GSTR * 4 + ks * 32);
#pragma unroll
            for (int np = 0; np < 4; np++) {
                uint32_t kh4[4], kl4[4];
                ldsm_x4(kh4, aBh + np * (16 * GSTR * 4) + ks * 32);
                ldsm_x4(kl4, aBl + np * (16 * GSTR * 4) + ks * 32);
                mma3(acc[0][2*np],   ah[0], al[0], kh4[0], kh4[1], kl4[0], kl4[1]);
                mma3(acc[0][2*np+1], ah[0], al[0], kh4[2], kh4[3], kl4[2], kl4[3]);
                mma3(acc[1][2*np],   ah[1], al[1], kh4[0], kh4[1], kl4[0], kl4[1]);
                mma3(acc[1][2*np+1], ah[1], al[1], kh4[2], kh4[3], kl4[2], kl4[3]);
            }
        }
    }
#pragma unroll
    for (int mt = 0; mt < 2; mt++)
#pragma unroll
        for (int nt = 0; nt < 8; nt++) {
            int col = col0 + nt * 8 + 2 * tig;
            size_t r0 = row0 + w * 32 + mt * 16 + g;
            float2 bi = *(const float2*)(bias + col);
            *(float2*)(out + r0 * DM + col) =
                make_float2(acc[mt][nt][0] + bi.x, acc[mt][nt][1] + bi.y);
            *(float2*)(out + (r0 + 8) * DM + col) =
                make_float2(acc[mt][nt][2] + bi.x, acc[mt][nt][3] + bi.y);
        }
}

// ============================================================
extern "C" void kernel_launch(void* const* d_in, const int* in_sizes, int n_in,
                              void* d_out, int out_size) {
    (void)in_sizes; (void)n_in; (void)out_size;
    const float* q    = (const float*)d_in[0];
    const float* k    = (const float*)d_in[1];
    const float* v    = (const float*)d_in[2];
    const float* mask = (const float*)d_in[3];
    const float* ow   = (const float*)d_in[4];
    const float* ob   = (const float*)d_in[5];
    float* out = (float*)d_out;

    cudaFuncSetAttribute(flash_kernel, cudaFuncAttributeMaxDynamicSharedMemorySize,
                         FLASH_SMEM_BYTES);
    cudaFuncSetAttribute(qt_mma_kernel, cudaFuncAttributeMaxDynamicSharedMemorySize,
                         QT_SMEM_BYTES);
    cudaFuncSetAttribute(out_mma_kernel, cudaFuncAttributeMaxDynamicSharedMemorySize,
                         QT_SMEM_BYTES);

    rope_kernel<<<dim3(SEQ / 32, BH), 256>>>(q, k);
    vT_kernel<<<dim3(SEQ / 64, BH), 256>>>(v);
    qt_mma_kernel<<<dim3(SEQ / 128, BH), 128, QT_SMEM_BYTES>>>(mask);
    flash_kernel<<<dim3(SEQ / 128, BH), 128, FLASH_SMEM_BYTES>>>();
    out_mma_kernel<<<dim3(NB * SEQ / 128, DM / 64), 128, QT_SMEM_BYTES>>>(ow, ob, out);
}